// round 8
// baseline (speedup 1.0000x reference)
#include <cuda_runtime.h>
#include <cuda_bf16.h>
#include <math.h>
#include <stdint.h>

#define NB    4
#define CCH   128
#define HW    4096            // 64*64 after 2x2 pool
#define KNN   16
#define PAIRS 65536           // HW*KNN per batch
#define NTILE 32              // col tiles per row
#define NEGINF (-3.4e38f)

// ======================= helpers =======================
__device__ __forceinline__ uint32_t smem_u32(const void* p) {
    uint32_t a;
    asm("{ .reg .u64 t; cvta.to.shared.u64 t, %1; cvt.u32.u64 %0, t; }" : "=r"(a) : "l"(p));
    return a;
}
__device__ __forceinline__ void ldm_x4(uint32_t* r, uint32_t a) {
    asm volatile("ldmatrix.sync.aligned.m8n8.x4.shared.b16 {%0,%1,%2,%3}, [%4];"
        : "=r"(r[0]), "=r"(r[1]), "=r"(r[2]), "=r"(r[3]) : "r"(a));
}
__device__ __forceinline__ void mma_bf16(float* c, const uint32_t* a, const uint32_t* b) {
    asm volatile("mma.sync.aligned.m16n8k16.row.col.f32.bf16.bf16.f32 "
        "{%0,%1,%2,%3}, {%4,%5,%6,%7}, {%8,%9}, {%0,%1,%2,%3};"
        : "+f"(c[0]), "+f"(c[1]), "+f"(c[2]), "+f"(c[3])
        : "r"(a[0]), "r"(a[1]), "r"(a[2]), "r"(a[3]), "r"(b[0]), "r"(b[1]));
}

// ======================= scratch (device globals) =======================
__device__ __align__(16) float g_pool[2][NB * CCH * HW];
__device__ __align__(16) float g_xt  [2][NB * HW * CCH];
__device__ __align__(16) __nv_bfloat16 g_xh[2][NB * HW * CCH];
__device__ __align__(16) float g_diag[2][NB * HW];
__device__ __align__(16) int2  g_cand[(size_t)2 * NB * HW * NTILE * KNN]; // 128MB
__device__              int   g_knn [2][NB * PAIRS];
__device__ __align__(16) float g_AB  [4][HW * CCH];
__device__ __align__(16) float g_partial[1024][256];
__device__ __align__(16) float g_m   [NB * 256];
__device__ __align__(16) float g_gate[NB * CCH];

// ---------------- 1) maxpool 2x2 ----------------
__global__ void k_pool(const float* __restrict__ rgb, const float* __restrict__ ir) {
    int o = blockIdx.x * blockDim.x + threadIdx.x;
    if (o >= NB * CCH * HW) return;
    int x  = o & 63;
    int y  = (o >> 6) & 63;
    int nc = o >> 12;
    int ib = nc * (128 * 128) + (2 * y) * 128 + 2 * x;
    {
        float a = rgb[ib], b = rgb[ib + 1], c = rgb[ib + 128], d = rgb[ib + 129];
        g_pool[0][o] = fmaxf(fmaxf(a, b), fmaxf(c, d));
    }
    {
        float a = ir[ib], b = ir[ib + 1], c = ir[ib + 128], d = ir[ib + 129];
        g_pool[1][o] = fmaxf(fmaxf(a, b), fmaxf(c, d));
    }
}

// ---------------- 2) transpose (n,c,hw) -> (n,hw,c) ----------------
__global__ void k_transpose() {
    __shared__ float s[32][33];
    int mod = blockIdx.z >> 2;
    int n   = blockIdx.z & 3;
    int hw0 = blockIdx.x * 32;
    int c0  = blockIdx.y * 32;
    const float* src = g_pool[mod] + (size_t)n * CCH * HW;
    float*       dst = g_xt[mod]  + (size_t)n * HW * CCH;
#pragma unroll
    for (int r = 0; r < 4; r++) {
        int c = c0 + threadIdx.y + 8 * r;
        s[threadIdx.y + 8 * r][threadIdx.x] = src[c * HW + hw0 + threadIdx.x];
    }
    __syncthreads();
#pragma unroll
    for (int r = 0; r < 4; r++) {
        int hw = hw0 + threadIdx.y + 8 * r;
        dst[hw * CCH + c0 + threadIdx.x] = s[threadIdx.x][threadIdx.y + 8 * r];
    }
}

// ---------------- 3) normalize rows -> bf16 + diag ----------------
__global__ void k_norm() {
    int mod  = blockIdx.y;
    int row  = blockIdx.x * 8 + (threadIdx.x >> 5);
    int lane = threadIdx.x & 31;
    const float4* src = (const float4*)(g_xt[mod] + (size_t)row * CCH);
    float4 v = src[lane];
    float ss = v.x * v.x + v.y * v.y + v.z * v.z + v.w * v.w;
#pragma unroll
    for (int off = 16; off > 0; off >>= 1) ss += __shfl_xor_sync(0xffffffff, ss, off);
    float nrm = sqrtf(ss);
    float inv = 1.0f / fmaxf(nrm, 1e-12f);
    union { __nv_bfloat16 b[4]; uint2 u; } ph;
    ph.b[0] = __float2bfloat16_rn(v.x * inv);
    ph.b[1] = __float2bfloat16_rn(v.y * inv);
    ph.b[2] = __float2bfloat16_rn(v.z * inv);
    ph.b[3] = __float2bfloat16_rn(v.w * inv);
    *((uint2*)(g_xh[mod] + (size_t)row * CCH) + lane) = ph.u;
    if (lane == 0) g_diag[mod][row] = ss * inv * inv;
}

// ---------------- 4) fused gram + warp-parallel per-tile top-16 ----------------
// smem: diag(1KB) + 2 bf16 operand tiles 128x136; score overlay 128x132 fp32 reuses them
#define TILE_STRIDE_B 272                 // 136 bf16 * 2
#define TILE_BYTES    (128 * TILE_STRIDE_B)
#define GS_DIAG 0
#define GS_AH   1024
#define GS_BH   (GS_AH + TILE_BYTES)
#define GS_SC   1024
#define GS_TOTAL (GS_AH + 2 * TILE_BYTES)   // 70656 B

__global__ void __launch_bounds__(256, 2) k_gram_sel() {
    extern __shared__ char smem[];
    uint32_t sb = smem_u32(smem);
    int tid = threadIdx.x, lane = tid & 31, w = tid >> 5;
    int bx = blockIdx.x, by = blockIdx.y;
    int mod = blockIdx.z >> 2, n = blockIdx.z & 3;

    const __nv_bfloat16* XH = g_xh[mod];
    int rowA0 = n * HW + by * 128;
    int rowB0 = n * HW + bx * 128;

    for (int i = tid; i < 2048; i += 256) {
        int r = i >> 4, ch = i & 15;
        uint32_t so = (uint32_t)r * TILE_STRIDE_B + (uint32_t)ch * 16u;
        *(uint4*)(smem + GS_AH + so) = *((const uint4*)(XH + (size_t)(rowA0 + r) * CCH) + ch);
        *(uint4*)(smem + GS_BH + so) = *((const uint4*)(XH + (size_t)(rowB0 + r) * CCH) + ch);
    }
    if (tid < 128) ((float*)(smem + GS_DIAG))[tid] = g_diag[mod][n * HW + bx * 128 + tid];
    __syncthreads();

    int wm = w >> 1, wn = w & 1;
    int m_base = wm * 32, n_base = wn * 64;

    float acc[2][8][4];
#pragma unroll
    for (int mf = 0; mf < 2; mf++)
#pragma unroll
        for (int nf = 0; nf < 8; nf++)
#pragma unroll
            for (int q = 0; q < 4; q++) acc[mf][nf][q] = 0.0f;

    int arow  = lane & 15;
    int acol8 = (lane >> 4) << 3;
    int brow  = ((lane >> 4) << 3) + (lane & 7);
    int bcol8 = ((lane >> 3) & 1) << 3;

    uint32_t aaddr = sb + GS_AH + (uint32_t)(m_base + arow) * TILE_STRIDE_B + (uint32_t)acol8 * 2u;
    uint32_t baddr = sb + GS_BH + (uint32_t)(n_base + brow) * TILE_STRIDE_B + (uint32_t)bcol8 * 2u;

#pragma unroll 2
    for (int k0 = 0; k0 < 128; k0 += 16) {
        uint32_t a[2][4], b[4][4];
        ldm_x4(a[0], aaddr + (uint32_t)k0 * 2u);
        ldm_x4(a[1], aaddr + 16u * TILE_STRIDE_B + (uint32_t)k0 * 2u);
#pragma unroll
        for (int q = 0; q < 4; q++)
            ldm_x4(b[q], baddr + (uint32_t)(q * 16) * TILE_STRIDE_B + (uint32_t)k0 * 2u);
#pragma unroll
        for (int mf = 0; mf < 2; mf++)
#pragma unroll
            for (int nf = 0; nf < 8; nf++)
                mma_bf16(acc[mf][nf], a[mf], &b[nf >> 1][(nf & 1) * 2]);
    }

    __syncthreads();   // all warps done reading operand smem

    // write scores = 2*g - diag_j into smem overlay (stride 132 floats)
    {
        const float* sd = (const float*)(smem + GS_DIAG);
        float* sc = (float*)(smem + GS_SC);
        int r_in  = lane >> 2;
        int cpair = (lane & 3) * 2;
#pragma unroll
        for (int mf = 0; mf < 2; mf++) {
            int rl = m_base + mf * 16 + r_in;
#pragma unroll
            for (int nf = 0; nf < 8; nf++) {
                int col = n_base + nf * 8 + cpair;
                float d0 = sd[col], d1 = sd[col + 1];
                sc[rl * 132 + col]           = 2.0f * acc[mf][nf][0] - d0;
                sc[rl * 132 + col + 1]       = 2.0f * acc[mf][nf][1] - d1;
                sc[(rl + 8) * 132 + col]     = 2.0f * acc[mf][nf][2] - d0;
                sc[(rl + 8) * 132 + col + 1] = 2.0f * acc[mf][nf][3] - d1;
            }
        }
    }
    __syncthreads();

    // warp-parallel per-row top-16 (16 rows per warp); static indexing only
    {
        const float* sc = (const float*)(smem + GS_SC);
        size_t cbase = (((size_t)(mod * NB + n) * HW + by * 128) * NTILE + bx) * KNN;
#pragma unroll 1
        for (int rr = 0; rr < 16; rr++) {
            int row = w * 16 + rr;
            const float* srow = sc + row * 132;
            float v0 = srow[lane];
            float v1 = srow[lane + 32];
            float v2 = srow[lane + 64];
            float v3 = srow[lane + 96];
            float cv = 0.0f; int ci = 0;
#pragma unroll 1
            for (int s = 0; s < KNN; s++) {
                float bv = v0; int bk = 0;
                if (v1 > bv) { bv = v1; bk = 1; }
                if (v2 > bv) { bv = v2; bk = 2; }
                if (v3 > bv) { bv = v3; bk = 3; }
                int bidx = lane + (bk << 5);
#pragma unroll
                for (int off = 16; off > 0; off >>= 1) {
                    float ov = __shfl_xor_sync(0xffffffff, bv, off);
                    int   oi = __shfl_xor_sync(0xffffffff, bidx, off);
                    if (ov > bv || (ov == bv && oi < bidx)) { bv = ov; bidx = oi; }
                }
                if (lane == s) { cv = bv; ci = bidx; }
                if ((bidx & 31) == lane) {
                    int kk = bidx >> 5;
                    if (kk == 0) v0 = NEGINF;
                    else if (kk == 1) v1 = NEGINF;
                    else if (kk == 2) v2 = NEGINF;
                    else v3 = NEGINF;
                }
            }
            int2* cp = g_cand + cbase + (size_t)row * (NTILE * KNN);
            if (lane < KNN) cp[lane] = make_int2(__float_as_int(cv), bx * 128 + ci);
        }
    }
}

// ---------------- 5) merge 512 candidates/row -> top-16 ----------------
__global__ void __launch_bounds__(128) k_merge() {
    __shared__ float sv[NTILE * KNN];
    __shared__ int   si[NTILE * KNN];
    __shared__ float wv[4];
    __shared__ int   wi_[4], wl_[4];
    int mod = blockIdx.z, n = blockIdx.y, row = blockIdx.x;
    int t = threadIdx.x, w = t >> 5, l = t & 31;
    const int2* cp = g_cand + ((size_t)(mod * NB + n) * HW + row) * (NTILE * KNN);
    for (int j = t; j < NTILE * KNN; j += 128) {
        int2 c = cp[j];
        sv[j] = __int_as_float(c.x);
        si[j] = c.y;
    }
    __syncthreads();

    int* out = g_knn[mod] + ((size_t)n * HW + row) * KNN;
#pragma unroll 1
    for (int s = 0; s < KNN; s++) {
        float best = NEGINF; int bidx = 0x7fffffff; int bloc = -1;
#pragma unroll
        for (int j = t; j < NTILE * KNN; j += 128) {
            float v = sv[j]; int ix = si[j];
            if (v > best || (v == best && ix < bidx)) { best = v; bidx = ix; bloc = j; }
        }
#pragma unroll
        for (int off = 16; off > 0; off >>= 1) {
            float ov = __shfl_xor_sync(0xffffffff, best, off);
            int   oi = __shfl_xor_sync(0xffffffff, bidx, off);
            int   ol = __shfl_xor_sync(0xffffffff, bloc, off);
            if (ov > best || (ov == best && oi < bidx)) { best = ov; bidx = oi; bloc = ol; }
        }
        if (l == 0) { wv[w] = best; wi_[w] = bidx; wl_[w] = bloc; }
        __syncthreads();
        if (t == 0) {
            float B = wv[0]; int I = wi_[0], L = wl_[0];
#pragma unroll
            for (int u = 1; u < 4; u++)
                if (wv[u] > B || (wv[u] == B && wi_[u] < I)) { B = wv[u]; I = wi_[u]; L = wl_[u]; }
            out[s] = I;
            sv[L] = NEGINF;
        }
        __syncthreads();
    }
}

// ---------------- 6) A/B tables ----------------
__global__ __launch_bounds__(256) void k_ab(const float* __restrict__ Wr,
                                            const float* __restrict__ Wi) {
    __shared__ float Xs[64][36];
    __shared__ float Ws[32][128];
    int which = blockIdx.y;
    const float* X  = (which == 0 || which == 3) ? g_xt[0] : g_xt[1];
    const float* Wg = (which < 2) ? Wr : Wi;
    bool both = (which == 0 || which == 2);
    int r0 = blockIdx.x * 64;
    int tx = threadIdx.x & 15, ty = threadIdx.x >> 4;

    float acc[4][8];
#pragma unroll
    for (int i = 0; i < 4; i++)
#pragma unroll
        for (int j = 0; j < 8; j++) acc[i][j] = 0.0f;

    for (int k0 = 0; k0 < 128; k0 += 32) {
#pragma unroll
        for (int p = 0; p < 2; p++) {
            int f4 = threadIdx.x + 256 * p;
            int r = f4 >> 3, kq = f4 & 7;
            *(float4*)(&Xs[r][kq * 4]) =
                *(const float4*)(X + (size_t)(r0 + r) * CCH + k0 + kq * 4);
        }
#pragma unroll
        for (int p = 0; p < 4; p++) {
            int f4 = threadIdx.x + 256 * p;
            int kk = f4 >> 5, cq = f4 & 31;
            float4 w = *(const float4*)(Wg + (size_t)(128 + k0 + kk) * CCH + cq * 4);
            if (both) {
                float4 w0 = *(const float4*)(Wg + (size_t)(k0 + kk) * CCH + cq * 4);
                w.x += w0.x; w.y += w0.y; w.z += w0.z; w.w += w0.w;
            }
            *(float4*)(&Ws[kk][cq * 4]) = w;
        }
        __syncthreads();
#pragma unroll 8
        for (int kk = 0; kk < 32; kk++) {
            float a[4], b[8];
#pragma unroll
            for (int i = 0; i < 4; i++) a[i] = Xs[ty + 16 * i][kk];
#pragma unroll
            for (int j = 0; j < 8; j++) b[j] = Ws[kk][tx + 16 * j];
#pragma unroll
            for (int i = 0; i < 4; i++)
#pragma unroll
                for (int j = 0; j < 8; j++) acc[i][j] += a[i] * b[j];
        }
        __syncthreads();
    }
#pragma unroll
    for (int i = 0; i < 4; i++)
#pragma unroll
        for (int j = 0; j < 8; j++)
            g_AB[which][(size_t)(r0 + ty + 16 * i) * CCH + tx + 16 * j] = acc[i][j];
}

// ---------------- 7) pair gather-mean ----------------
__global__ __launch_bounds__(128) void k_pair(const float* __restrict__ br,
                                              const float* __restrict__ bi) {
    __shared__ int sp[256], sq[256];
    int n = blockIdx.y;
    int base = n * PAIRS + blockIdx.x * 256;
    for (int t = threadIdx.x; t < 256; t += 128) {
        sp[t] = g_knn[0][base + t];
        sq[t] = g_knn[1][base + t];
    }
    __syncthreads();
    int c = threadIdx.x;
    float brc = br[c], bic = bi[c];
    float aR = 0.0f, aI = 0.0f;
#pragma unroll 4
    for (int t = 0; t < 256; t++) {
        int p = sp[t], q = sq[t];
        float fr = g_AB[0][p * CCH + c] - g_AB[1][q * CCH + c] + brc;
        aR += (fr >= 0.0f) ? fr : 0.01f * fr;
        float fi = g_AB[2][q * CCH + c] - g_AB[3][p * CCH + c] + bic;
        aI += (fi >= 0.0f) ? fi : 0.01f * fi;
    }
    int b = n * 256 + blockIdx.x;
    g_partial[b][c]       = aR;
    g_partial[b][c + 128] = aI;
}

// ---------------- 8) reduce -> m ----------------
__global__ void k_reduce_m() {
    int n = blockIdx.x, d = threadIdx.x;
    float s = 0.0f;
    for (int bb = 0; bb < 256; bb++) s += g_partial[n * 256 + bb][d];
    g_m[n * 256 + d] = s * (1.0f / (float)PAIRS);
}

// ---------------- 9) SE gate ----------------
__global__ void k_se(const float* __restrict__ w1, const float* __restrict__ b1,
                     const float* __restrict__ w2, const float* __restrict__ b2) {
    __shared__ float tm[NB][8];
    int tid = threadIdx.x;
    if (tid < 32) {
        int n = tid >> 3, j = tid & 7;
        float s = b1[j];
        for (int d = 0; d < 256; d++) s += g_m[n * 256 + d] * w1[d * 8 + j];
        tm[n][j] = (s >= 0.0f) ? s : 0.01f * s;
    }
    __syncthreads();
    int n = tid >> 7, c = tid & 127;
    float s = b2[c];
#pragma unroll
    for (int j = 0; j < 8; j++) s += tm[n][j] * w2[j * 128 + c];
    g_gate[n * 128 + c] = 1.0f / (1.0f + expf(-s));
}

// ---------------- 10) gated blend + relu ----------------
__global__ void k_out(const float* __restrict__ g1, const float* __restrict__ g2,
                      float* __restrict__ out) {
    int o = blockIdx.x * blockDim.x + threadIdx.x;
    if (o >= NB * CCH * HW) return;
    int nc = o >> 12;
    float g = g_gate[nc];
    float v = g1[0] * g * g_pool[0][o] + g2[0] * (1.0f - g) * g_pool[1][o];
    out[o] = fmaxf(v, 0.0f);
}

// ---------------- launch ----------------
extern "C" void kernel_launch(void* const* d_in, const int* in_sizes, int n_in,
                              void* d_out, int out_size) {
    const float* rgb = (const float*)d_in[0];
    const float* ir  = (const float*)d_in[1];
    const float* Wr  = (const float*)d_in[2];
    const float* br  = (const float*)d_in[3];
    const float* Wi  = (const float*)d_in[4];
    const float* bi  = (const float*)d_in[5];
    const float* w1  = (const float*)d_in[6];
    const float* b1  = (const float*)d_in[7];
    const float* w2  = (const float*)d_in[8];
    const float* b2  = (const float*)d_in[9];
    const float* g1  = (const float*)d_in[10];
    const float* g2  = (const float*)d_in[11];
    float* out = (float*)d_out;

    cudaFuncSetAttribute(k_gram_sel, cudaFuncAttributeMaxDynamicSharedMemorySize, GS_TOTAL);

    k_pool<<<8192, 256>>>(rgb, ir);
    k_transpose<<<dim3(128, 4, 8), dim3(32, 8)>>>();
    k_norm<<<dim3(2048, 2), 256>>>();
    k_ab<<<dim3(64, 4), 256>>>(Wr, Wi);

    k_gram_sel<<<dim3(32, 32, 8), 256, GS_TOTAL>>>();   // gram + fused warp-parallel top-16
    k_merge<<<dim3(4096, 4, 2), 128>>>();               // 512 candidates -> top-16 per row

    k_pair<<<dim3(256, 4), 128>>>(br, bi);
    k_reduce_m<<<4, 256>>>();
    k_se<<<1, 512>>>(w1, b1, w2, b2);
    k_out<<<8192, 256>>>(g1, g2, out);
}

// round 9
// speedup vs baseline: 5.5775x; 5.5775x over previous
#include <cuda_runtime.h>
#include <cuda_bf16.h>
#include <cuda_fp16.h>
#include <math.h>
#include <stdint.h>

#define NB    4
#define CCH   128
#define HW    4096            // 64*64 after 2x2 pool
#define KNN   16
#define PAIRS 65536           // HW*KNN per batch
#define NEGINF (-3.4e38f)

// ======================= helpers =======================
__device__ __forceinline__ uint32_t smem_u32(const void* p) {
    uint32_t a;
    asm("{ .reg .u64 t; cvta.to.shared.u64 t, %1; cvt.u32.u64 %0, t; }" : "=r"(a) : "l"(p));
    return a;
}
__device__ __forceinline__ void ldm_x4(uint32_t* r, uint32_t a) {
    asm volatile("ldmatrix.sync.aligned.m8n8.x4.shared.b16 {%0,%1,%2,%3}, [%4];"
        : "=r"(r[0]), "=r"(r[1]), "=r"(r[2]), "=r"(r[3]) : "r"(a));
}
__device__ __forceinline__ void mma_bf16(float* c, const uint32_t* a, const uint32_t* b) {
    asm volatile("mma.sync.aligned.m16n8k16.row.col.f32.bf16.bf16.f32 "
        "{%0,%1,%2,%3}, {%4,%5,%6,%7}, {%8,%9}, {%0,%1,%2,%3};"
        : "+f"(c[0]), "+f"(c[1]), "+f"(c[2]), "+f"(c[3])
        : "r"(a[0]), "r"(a[1]), "r"(a[2]), "r"(a[3]), "r"(b[0]), "r"(b[1]));
}

// ======================= scratch (device globals) =======================
__device__ __align__(16) float g_pool[2][NB * CCH * HW];
__device__ __align__(16) float g_xt  [2][NB * HW * CCH];
__device__ __align__(16) __nv_bfloat16 g_xh[2][NB * HW * CCH];
__device__ __align__(16) float g_diag[2][NB * HW];
__device__ __align__(16) __half g_scoresh[2][(size_t)NB * HW * HW]; // 2 x 128MB
__device__              int   g_knn [2][NB * PAIRS];
__device__ __align__(16) float g_AB  [4][HW * CCH];
__device__ __align__(16) float g_partial[1024][256];
__device__ __align__(16) float g_m   [NB * 256];
__device__ __align__(16) float g_gate[NB * CCH];

// ---------------- 1) maxpool 2x2 ----------------
__global__ void k_pool(const float* __restrict__ rgb, const float* __restrict__ ir) {
    int o = blockIdx.x * blockDim.x + threadIdx.x;
    if (o >= NB * CCH * HW) return;
    int x  = o & 63;
    int y  = (o >> 6) & 63;
    int nc = o >> 12;
    int ib = nc * (128 * 128) + (2 * y) * 128 + 2 * x;
    {
        float a = rgb[ib], b = rgb[ib + 1], c = rgb[ib + 128], d = rgb[ib + 129];
        g_pool[0][o] = fmaxf(fmaxf(a, b), fmaxf(c, d));
    }
    {
        float a = ir[ib], b = ir[ib + 1], c = ir[ib + 128], d = ir[ib + 129];
        g_pool[1][o] = fmaxf(fmaxf(a, b), fmaxf(c, d));
    }
}

// ---------------- 2) transpose (n,c,hw) -> (n,hw,c) ----------------
__global__ void k_transpose() {
    __shared__ float s[32][33];
    int mod = blockIdx.z >> 2;
    int n   = blockIdx.z & 3;
    int hw0 = blockIdx.x * 32;
    int c0  = blockIdx.y * 32;
    const float* src = g_pool[mod] + (size_t)n * CCH * HW;
    float*       dst = g_xt[mod]  + (size_t)n * HW * CCH;
#pragma unroll
    for (int r = 0; r < 4; r++) {
        int c = c0 + threadIdx.y + 8 * r;
        s[threadIdx.y + 8 * r][threadIdx.x] = src[c * HW + hw0 + threadIdx.x];
    }
    __syncthreads();
#pragma unroll
    for (int r = 0; r < 4; r++) {
        int hw = hw0 + threadIdx.y + 8 * r;
        dst[hw * CCH + c0 + threadIdx.x] = s[threadIdx.x][threadIdx.y + 8 * r];
    }
}

// ---------------- 3) normalize rows -> bf16 + diag ----------------
__global__ void k_norm() {
    int mod  = blockIdx.y;
    int row  = blockIdx.x * 8 + (threadIdx.x >> 5);
    int lane = threadIdx.x & 31;
    const float4* src = (const float4*)(g_xt[mod] + (size_t)row * CCH);
    float4 v = src[lane];
    float ss = v.x * v.x + v.y * v.y + v.z * v.z + v.w * v.w;
#pragma unroll
    for (int off = 16; off > 0; off >>= 1) ss += __shfl_xor_sync(0xffffffff, ss, off);
    float nrm = sqrtf(ss);
    float inv = 1.0f / fmaxf(nrm, 1e-12f);
    union { __nv_bfloat16 b[4]; uint2 u; } ph;
    ph.b[0] = __float2bfloat16_rn(v.x * inv);
    ph.b[1] = __float2bfloat16_rn(v.y * inv);
    ph.b[2] = __float2bfloat16_rn(v.z * inv);
    ph.b[3] = __float2bfloat16_rn(v.w * inv);
    *((uint2*)(g_xh[mod] + (size_t)row * CCH) + lane) = ph.u;
    if (lane == 0) g_diag[mod][row] = ss * inv * inv;
}

// ---------------- 4) mma.sync bf16 gram tile -> fp16 scores = 2g - diag_j ----------------
#define TILE_STRIDE_B 272                 // 136 bf16 * 2
#define TILE_BYTES    (128 * TILE_STRIDE_B)
#define GS_DIAG 0
#define GS_AH   1024
#define GS_BH   (GS_AH + TILE_BYTES)
#define GS_TOTAL (GS_AH + 2 * TILE_BYTES)   // 70656 B

__global__ void __launch_bounds__(256, 2) k_gram_mma() {
    extern __shared__ char smem[];
    uint32_t sb = smem_u32(smem);
    int tid = threadIdx.x, lane = tid & 31, w = tid >> 5;
    int bx = blockIdx.x, by = blockIdx.y;
    int mod = blockIdx.z >> 2, n = blockIdx.z & 3;

    const __nv_bfloat16* XH = g_xh[mod];
    int rowA0 = n * HW + by * 128;
    int rowB0 = n * HW + bx * 128;

    for (int i = tid; i < 2048; i += 256) {
        int r = i >> 4, ch = i & 15;
        uint32_t so = (uint32_t)r * TILE_STRIDE_B + (uint32_t)ch * 16u;
        *(uint4*)(smem + GS_AH + so) = *((const uint4*)(XH + (size_t)(rowA0 + r) * CCH) + ch);
        *(uint4*)(smem + GS_BH + so) = *((const uint4*)(XH + (size_t)(rowB0 + r) * CCH) + ch);
    }
    if (tid < 128) ((float*)(smem + GS_DIAG))[tid] = g_diag[mod][n * HW + bx * 128 + tid];
    __syncthreads();

    int wm = w >> 1, wn = w & 1;
    int m_base = wm * 32, n_base = wn * 64;

    float acc[2][8][4];
#pragma unroll
    for (int mf = 0; mf < 2; mf++)
#pragma unroll
        for (int nf = 0; nf < 8; nf++)
#pragma unroll
            for (int q = 0; q < 4; q++) acc[mf][nf][q] = 0.0f;

    int arow  = lane & 15;
    int acol8 = (lane >> 4) << 3;
    int brow  = ((lane >> 4) << 3) + (lane & 7);
    int bcol8 = ((lane >> 3) & 1) << 3;

    uint32_t aaddr = sb + GS_AH + (uint32_t)(m_base + arow) * TILE_STRIDE_B + (uint32_t)acol8 * 2u;
    uint32_t baddr = sb + GS_BH + (uint32_t)(n_base + brow) * TILE_STRIDE_B + (uint32_t)bcol8 * 2u;

#pragma unroll 2
    for (int k0 = 0; k0 < 128; k0 += 16) {
        uint32_t a[2][4], b[4][4];
        ldm_x4(a[0], aaddr + (uint32_t)k0 * 2u);
        ldm_x4(a[1], aaddr + 16u * TILE_STRIDE_B + (uint32_t)k0 * 2u);
#pragma unroll
        for (int q = 0; q < 4; q++)
            ldm_x4(b[q], baddr + (uint32_t)(q * 16) * TILE_STRIDE_B + (uint32_t)k0 * 2u);
#pragma unroll
        for (int mf = 0; mf < 2; mf++)
#pragma unroll
            for (int nf = 0; nf < 8; nf++)
                mma_bf16(acc[mf][nf], a[mf], &b[nf >> 1][(nf & 1) * 2]);
    }

    // epilogue: fp16 scores = 2*g - diag_j
    const float* sd = (const float*)(smem + GS_DIAG);
    int r_in  = lane >> 2;
    int cpair = (lane & 3) * 2;
    __half* Gout = g_scoresh[mod] + (size_t)n * HW * HW;
#pragma unroll
    for (int mf = 0; mf < 2; mf++) {
        int row0 = by * 128 + m_base + mf * 16 + r_in;
#pragma unroll
        for (int nf = 0; nf < 8; nf++) {
            int col = n_base + nf * 8 + cpair;
            float d0 = sd[col], d1 = sd[col + 1];
            __half2 p0 = __halves2half2(__float2half_rn(2.0f * acc[mf][nf][0] - d0),
                                        __float2half_rn(2.0f * acc[mf][nf][1] - d1));
            __half2 p1 = __halves2half2(__float2half_rn(2.0f * acc[mf][nf][2] - d0),
                                        __float2half_rn(2.0f * acc[mf][nf][3] - d1));
            *(__half2*)(Gout + (size_t)row0 * HW + bx * 128 + col) = p0;
            *(__half2*)(Gout + (size_t)(row0 + 8) * HW + bx * 128 + col) = p1;
        }
    }
}

// ---------------- 5) per-row top-16 via packed keys + REDUX ----------------
// key = (ordered_fp16 << 12) | (4095 - j): u32 max == (max score, min index)
__global__ void __launch_bounds__(256) k_topk() {
    __shared__ uint32_t sc[HW];     // 16KB keys
    __shared__ uint32_t wv[2][8];
    __shared__ uint32_t bc[2];
    int mod = blockIdx.z, n = blockIdx.y, i = blockIdx.x;
    int t = threadIdx.x, w = t >> 5, l = t & 31;
    const uint32_t* S = (const uint32_t*)(g_scoresh[mod]
                         + (size_t)n * HW * HW + (size_t)i * HW);

    uint32_t myKey = 0;
#pragma unroll
    for (int step = 0; step < 8; step++) {
        int j = 2 * t + 512 * step;
        uint32_t pk = S[j >> 1];
        uint32_t h0 = pk & 0xFFFFu, h1 = pk >> 16;
        uint32_t o0 = (h0 & 0x8000u) ? (~h0 & 0xFFFFu) : (h0 | 0x8000u);
        uint32_t o1 = (h1 & 0x8000u) ? (~h1 & 0xFFFFu) : (h1 | 0x8000u);
        uint32_t k0 = (o0 << 12) | (uint32_t)(4095 - j);
        uint32_t k1 = (o1 << 12) | (uint32_t)(4094 - j);
        sc[j] = k0; sc[j + 1] = k1;
        myKey = max(myKey, max(k0, k1));
    }
    __syncthreads();

    int* out = g_knn[mod] + ((size_t)n * HW + i) * KNN;
#pragma unroll 1
    for (int s = 0; s < KNN; s++) {
        int pb = s & 1;
        uint32_t wk = __reduce_max_sync(0xffffffffu, myKey);
        if (l == 0) wv[pb][w] = wk;
        __syncthreads();
        if (t == 0) {
            uint32_t B = wv[pb][0];
#pragma unroll
            for (int u = 1; u < 8; u++) B = max(B, wv[pb][u]);
            bc[pb] = B;
            out[s] = 4095 - (int)(B & 0xFFFu);
        }
        __syncthreads();
        uint32_t best = bc[pb];
        if (myKey == best) {   // unique owner (index embedded in key)
            int jwin = 4095 - (int)(best & 0xFFFu);
            sc[jwin] = 0;
            uint32_t nk = 0;
#pragma unroll
            for (int step = 0; step < 8; step++) {
                int j = 2 * t + 512 * step;
                nk = max(nk, max(sc[j], sc[j + 1]));
            }
            myKey = nk;
        }
    }
}

// ---------------- 6) A/B tables ----------------
__global__ __launch_bounds__(256) void k_ab(const float* __restrict__ Wr,
                                            const float* __restrict__ Wi) {
    __shared__ float Xs[64][36];
    __shared__ float Ws[32][128];
    int which = blockIdx.y;
    const float* X  = (which == 0 || which == 3) ? g_xt[0] : g_xt[1];
    const float* Wg = (which < 2) ? Wr : Wi;
    bool both = (which == 0 || which == 2);
    int r0 = blockIdx.x * 64;
    int tx = threadIdx.x & 15, ty = threadIdx.x >> 4;

    float acc[4][8];
#pragma unroll
    for (int i = 0; i < 4; i++)
#pragma unroll
        for (int j = 0; j < 8; j++) acc[i][j] = 0.0f;

    for (int k0 = 0; k0 < 128; k0 += 32) {
#pragma unroll
        for (int p = 0; p < 2; p++) {
            int f4 = threadIdx.x + 256 * p;
            int r = f4 >> 3, kq = f4 & 7;
            *(float4*)(&Xs[r][kq * 4]) =
                *(const float4*)(X + (size_t)(r0 + r) * CCH + k0 + kq * 4);
        }
#pragma unroll
        for (int p = 0; p < 4; p++) {
            int f4 = threadIdx.x + 256 * p;
            int kk = f4 >> 5, cq = f4 & 31;
            float4 w = *(const float4*)(Wg + (size_t)(128 + k0 + kk) * CCH + cq * 4);
            if (both) {
                float4 w0 = *(const float4*)(Wg + (size_t)(k0 + kk) * CCH + cq * 4);
                w.x += w0.x; w.y += w0.y; w.z += w0.z; w.w += w0.w;
            }
            *(float4*)(&Ws[kk][cq * 4]) = w;
        }
        __syncthreads();
#pragma unroll 8
        for (int kk = 0; kk < 32; kk++) {
            float a[4], b[8];
#pragma unroll
            for (int i = 0; i < 4; i++) a[i] = Xs[ty + 16 * i][kk];
#pragma unroll
            for (int j = 0; j < 8; j++) b[j] = Ws[kk][tx + 16 * j];
#pragma unroll
            for (int i = 0; i < 4; i++)
#pragma unroll
                for (int j = 0; j < 8; j++) acc[i][j] += a[i] * b[j];
        }
        __syncthreads();
    }
#pragma unroll
    for (int i = 0; i < 4; i++)
#pragma unroll
        for (int j = 0; j < 8; j++)
            g_AB[which][(size_t)(r0 + ty + 16 * i) * CCH + tx + 16 * j] = acc[i][j];
}

// ---------------- 7) pair gather-mean ----------------
__global__ __launch_bounds__(128) void k_pair(const float* __restrict__ br,
                                              const float* __restrict__ bi) {
    __shared__ int sp[256], sq[256];
    int n = blockIdx.y;
    int base = n * PAIRS + blockIdx.x * 256;
    for (int t = threadIdx.x; t < 256; t += 128) {
        sp[t] = g_knn[0][base + t];
        sq[t] = g_knn[1][base + t];
    }
    __syncthreads();
    int c = threadIdx.x;
    float brc = br[c], bic = bi[c];
    float aR = 0.0f, aI = 0.0f;
#pragma unroll 4
    for (int t = 0; t < 256; t++) {
        int p = sp[t], q = sq[t];
        float fr = g_AB[0][p * CCH + c] - g_AB[1][q * CCH + c] + brc;
        aR += (fr >= 0.0f) ? fr : 0.01f * fr;
        float fi = g_AB[2][q * CCH + c] - g_AB[3][p * CCH + c] + bic;
        aI += (fi >= 0.0f) ? fi : 0.01f * fi;
    }
    int b = n * 256 + blockIdx.x;
    g_partial[b][c]       = aR;
    g_partial[b][c + 128] = aI;
}

// ---------------- 8) reduce -> m ----------------
__global__ void k_reduce_m() {
    int n = blockIdx.x, d = threadIdx.x;
    float s = 0.0f;
    for (int bb = 0; bb < 256; bb++) s += g_partial[n * 256 + bb][d];
    g_m[n * 256 + d] = s * (1.0f / (float)PAIRS);
}

// ---------------- 9) SE gate ----------------
__global__ void k_se(const float* __restrict__ w1, const float* __restrict__ b1,
                     const float* __restrict__ w2, const float* __restrict__ b2) {
    __shared__ float tm[NB][8];
    int tid = threadIdx.x;
    if (tid < 32) {
        int n = tid >> 3, j = tid & 7;
        float s = b1[j];
        for (int d = 0; d < 256; d++) s += g_m[n * 256 + d] * w1[d * 8 + j];
        tm[n][j] = (s >= 0.0f) ? s : 0.01f * s;
    }
    __syncthreads();
    int n = tid >> 7, c = tid & 127;
    float s = b2[c];
#pragma unroll
    for (int j = 0; j < 8; j++) s += tm[n][j] * w2[j * 128 + c];
    g_gate[n * 128 + c] = 1.0f / (1.0f + expf(-s));
}

// ---------------- 10) gated blend + relu ----------------
__global__ void k_out(const float* __restrict__ g1, const float* __restrict__ g2,
                      float* __restrict__ out) {
    int o = blockIdx.x * blockDim.x + threadIdx.x;
    if (o >= NB * CCH * HW) return;
    int nc = o >> 12;
    float g = g_gate[nc];
    float v = g1[0] * g * g_pool[0][o] + g2[0] * (1.0f - g) * g_pool[1][o];
    out[o] = fmaxf(v, 0.0f);
}

// ---------------- launch ----------------
extern "C" void kernel_launch(void* const* d_in, const int* in_sizes, int n_in,
                              void* d_out, int out_size) {
    const float* rgb = (const float*)d_in[0];
    const float* ir  = (const float*)d_in[1];
    const float* Wr  = (const float*)d_in[2];
    const float* br  = (const float*)d_in[3];
    const float* Wi  = (const float*)d_in[4];
    const float* bi  = (const float*)d_in[5];
    const float* w1  = (const float*)d_in[6];
    const float* b1  = (const float*)d_in[7];
    const float* w2  = (const float*)d_in[8];
    const float* b2  = (const float*)d_in[9];
    const float* g1  = (const float*)d_in[10];
    const float* g2  = (const float*)d_in[11];
    float* out = (float*)d_out;

    cudaFuncSetAttribute(k_gram_mma, cudaFuncAttributeMaxDynamicSharedMemorySize, GS_TOTAL);

    k_pool<<<8192, 256>>>(rgb, ir);
    k_transpose<<<dim3(128, 4, 8), dim3(32, 8)>>>();
    k_norm<<<dim3(2048, 2), 256>>>();
    k_ab<<<dim3(64, 4), 256>>>(Wr, Wi);

    k_gram_mma<<<dim3(32, 32, 8), 256, GS_TOTAL>>>();   // bf16 gram -> fp16 scores
    k_topk<<<dim3(4096, 4, 2), 256>>>();                // packed-key REDUX top-16

    k_pair<<<dim3(256, 4), 128>>>(br, bi);
    k_reduce_m<<<4, 256>>>();
    k_se<<<1, 512>>>(w1, b1, w2, b2);
    k_out<<<8192, 256>>>(g1, g2, out);
}

// round 10
// speedup vs baseline: 6.0373x; 1.0824x over previous
#include <cuda_runtime.h>
#include <cuda_bf16.h>
#include <cuda_fp16.h>
#include <math.h>
#include <stdint.h>

#define NB    4
#define CCH   128
#define HW    4096            // 64*64 after 2x2 pool
#define KNN   16
#define PAIRS 65536           // HW*KNN per batch
#define NEGINF (-3.4e38f)

// ======================= helpers =======================
__device__ __forceinline__ uint32_t smem_u32(const void* p) {
    uint32_t a;
    asm("{ .reg .u64 t; cvta.to.shared.u64 t, %1; cvt.u32.u64 %0, t; }" : "=r"(a) : "l"(p));
    return a;
}
__device__ __forceinline__ void ldm_x4(uint32_t* r, uint32_t a) {
    asm volatile("ldmatrix.sync.aligned.m8n8.x4.shared.b16 {%0,%1,%2,%3}, [%4];"
        : "=r"(r[0]), "=r"(r[1]), "=r"(r[2]), "=r"(r[3]) : "r"(a));
}
__device__ __forceinline__ void mma_bf16(float* c, const uint32_t* a, const uint32_t* b) {
    asm volatile("mma.sync.aligned.m16n8k16.row.col.f32.bf16.bf16.f32 "
        "{%0,%1,%2,%3}, {%4,%5,%6,%7}, {%8,%9}, {%0,%1,%2,%3};"
        : "+f"(c[0]), "+f"(c[1]), "+f"(c[2]), "+f"(c[3])
        : "r"(a[0]), "r"(a[1]), "r"(a[2]), "r"(a[3]), "r"(b[0]), "r"(b[1]));
}

// ======================= scratch (device globals) =======================
__device__ __align__(16) float g_pool[2][NB * CCH * HW];
__device__ __align__(16) float g_xt  [2][HW * CCH];                 // batch 0 only
__device__ __align__(16) __nv_bfloat16 g_xh[2][NB * HW * CCH];
__device__ __align__(16) float g_diag[2][NB * HW];
__device__ __align__(16) __half g_scoresh[2][(size_t)NB * HW * HW]; // 2 x 128MB
__device__              int   g_knn [2][NB * PAIRS];
__device__ __align__(16) float g_AB  [4][HW * CCH];
__device__ __align__(16) float g_partial[1024][256];
__device__ __align__(16) float g_m   [NB * 256];
__device__ __align__(16) float g_gate[NB * CCH];

// ---------------- 1) maxpool 2x2 ----------------
__global__ void k_pool(const float* __restrict__ rgb, const float* __restrict__ ir) {
    int o = blockIdx.x * blockDim.x + threadIdx.x;
    if (o >= NB * CCH * HW) return;
    int x  = o & 63;
    int y  = (o >> 6) & 63;
    int nc = o >> 12;
    int ib = nc * (128 * 128) + (2 * y) * 128 + 2 * x;
    {
        float a = rgb[ib], b = rgb[ib + 1], c = rgb[ib + 128], d = rgb[ib + 129];
        g_pool[0][o] = fmaxf(fmaxf(a, b), fmaxf(c, d));
    }
    {
        float a = ir[ib], b = ir[ib + 1], c = ir[ib + 128], d = ir[ib + 129];
        g_pool[1][o] = fmaxf(fmaxf(a, b), fmaxf(c, d));
    }
}

// ---------------- 2) fused transpose + normalize -> bf16 xh, diag, xt(batch0) ----------------
__global__ void __launch_bounds__(256) k_tnorm() {
    __shared__ float s[128][33];
    int mod = blockIdx.z, n = blockIdx.y, hw0 = blockIdx.x * 32;
    const float* src = g_pool[mod] + (size_t)n * CCH * HW + hw0;
#pragma unroll
    for (int p = 0; p < 16; p++) {
        int i = threadIdx.x + 256 * p;      // 128c x 32hw
        int c = i >> 5, hl = i & 31;
        s[c][hl] = src[(size_t)c * HW + hl];
    }
    __syncthreads();
    int w = threadIdx.x >> 5, l = threadIdx.x & 31;
#pragma unroll
    for (int m = 0; m < 4; m++) {
        int hw = w * 4 + m;
        float a0 = s[l][hw], a1 = s[l + 32][hw], a2 = s[l + 64][hw], a3 = s[l + 96][hw];
        float ss = a0 * a0 + a1 * a1 + a2 * a2 + a3 * a3;
#pragma unroll
        for (int off = 16; off > 0; off >>= 1) ss += __shfl_xor_sync(0xffffffff, ss, off);
        float inv = 1.0f / fmaxf(sqrtf(ss), 1e-12f);
        union { __nv_bfloat16 b[2]; uint32_t u; } w0, w1;
        w0.b[0] = __float2bfloat16_rn(s[2 * l][hw] * inv);
        w0.b[1] = __float2bfloat16_rn(s[2 * l + 1][hw] * inv);
        w1.b[0] = __float2bfloat16_rn(s[2 * l + 64][hw] * inv);
        w1.b[1] = __float2bfloat16_rn(s[2 * l + 65][hw] * inv);
        uint32_t* dst = (uint32_t*)(g_xh[mod] + (size_t)(n * HW + hw0 + hw) * CCH);
        dst[l] = w0.u;
        dst[l + 32] = w1.u;
        if (n == 0) {
            float* xd = g_xt[mod] + (size_t)(hw0 + hw) * CCH;
            xd[l] = a0; xd[l + 32] = a1; xd[l + 64] = a2; xd[l + 96] = a3;
        }
        if (l == 0) g_diag[mod][n * HW + hw0 + hw] = ss * inv * inv;
    }
}

// ---------------- 3) triangular bf16 gram -> fp16 scores (direct + mirror) ----------------
#define TILE_STRIDE_B 272                 // 136 bf16 * 2
#define TILE_BYTES    (128 * TILE_STRIDE_B)
#define GS_DIAGA 0
#define GS_DIAGB 512
#define GS_AH    1024
#define GS_BH    (GS_AH + TILE_BYTES)
#define GS_SC    1024                     // fp32 overlay 128 x 129 = 66048 B (fits in operands)
#define SC_STR   129
#define GS_TOTAL (GS_AH + 2 * TILE_BYTES)   // 70656 B

__global__ void __launch_bounds__(256, 2) k_gram_tri() {
    extern __shared__ char smem[];
    uint32_t sb = smem_u32(smem);
    int tid = threadIdx.x, lane = tid & 31, w = tid >> 5;
    int t = blockIdx.x;
    int mod = blockIdx.y >> 2, n = blockIdx.y & 3;

    int by = (int)((sqrtf(8.0f * t + 1.0f) - 1.0f) * 0.5f);
    while ((by + 1) * (by + 2) / 2 <= t) by++;
    while (by * (by + 1) / 2 > t) by--;
    int bx = t - by * (by + 1) / 2;       // bx <= by

    const __nv_bfloat16* XH = g_xh[mod];
    int rowA0 = n * HW + by * 128;
    int rowB0 = n * HW + bx * 128;

    for (int i = tid; i < 2048; i += 256) {
        int r = i >> 4, ch = i & 15;
        uint32_t so = (uint32_t)r * TILE_STRIDE_B + (uint32_t)ch * 16u;
        *(uint4*)(smem + GS_AH + so) = *((const uint4*)(XH + (size_t)(rowA0 + r) * CCH) + ch);
        *(uint4*)(smem + GS_BH + so) = *((const uint4*)(XH + (size_t)(rowB0 + r) * CCH) + ch);
    }
    if (tid < 128)      ((float*)(smem + GS_DIAGA))[tid] = g_diag[mod][n * HW + by * 128 + tid];
    else                ((float*)(smem + GS_DIAGB))[tid - 128] =
                            g_diag[mod][n * HW + bx * 128 + (tid - 128)];
    __syncthreads();

    int wm = w >> 1, wn = w & 1;
    int m_base = wm * 32, n_base = wn * 64;

    float acc[2][8][4];
#pragma unroll
    for (int mf = 0; mf < 2; mf++)
#pragma unroll
        for (int nf = 0; nf < 8; nf++)
#pragma unroll
            for (int q = 0; q < 4; q++) acc[mf][nf][q] = 0.0f;

    int arow  = lane & 15;
    int acol8 = (lane >> 4) << 3;
    int brow  = ((lane >> 4) << 3) + (lane & 7);
    int bcol8 = ((lane >> 3) & 1) << 3;

    uint32_t aaddr = sb + GS_AH + (uint32_t)(m_base + arow) * TILE_STRIDE_B + (uint32_t)acol8 * 2u;
    uint32_t baddr = sb + GS_BH + (uint32_t)(n_base + brow) * TILE_STRIDE_B + (uint32_t)bcol8 * 2u;

#pragma unroll 2
    for (int k0 = 0; k0 < 128; k0 += 16) {
        uint32_t a[2][4], b[4][4];
        ldm_x4(a[0], aaddr + (uint32_t)k0 * 2u);
        ldm_x4(a[1], aaddr + 16u * TILE_STRIDE_B + (uint32_t)k0 * 2u);
#pragma unroll
        for (int q = 0; q < 4; q++)
            ldm_x4(b[q], baddr + (uint32_t)(q * 16) * TILE_STRIDE_B + (uint32_t)k0 * 2u);
#pragma unroll
        for (int mf = 0; mf < 2; mf++)
#pragma unroll
            for (int nf = 0; nf < 8; nf++)
                mma_bf16(acc[mf][nf], a[mf], &b[nf >> 1][(nf & 1) * 2]);
    }

    __syncthreads();   // operands dead; overlay them with raw g

    {
        float* sc = (float*)(smem + GS_SC);
        int r_in  = lane >> 2;
        int cpair = (lane & 3) * 2;
#pragma unroll
        for (int mf = 0; mf < 2; mf++) {
            int rl = m_base + mf * 16 + r_in;
#pragma unroll
            for (int nf = 0; nf < 8; nf++) {
                int col = n_base + nf * 8 + cpair;
                sc[rl * SC_STR + col]           = acc[mf][nf][0];
                sc[rl * SC_STR + col + 1]       = acc[mf][nf][1];
                sc[(rl + 8) * SC_STR + col]     = acc[mf][nf][2];
                sc[(rl + 8) * SC_STR + col + 1] = acc[mf][nf][3];
            }
        }
    }
    __syncthreads();

    const float* sc = (const float*)(smem + GS_SC);
    const float* dA = (const float*)(smem + GS_DIAGA);
    const float* dB = (const float*)(smem + GS_DIAGB);
    __half* G = g_scoresh[mod] + (size_t)n * HW * HW;

    // direct: rows in by-block, cols in bx-block
#pragma unroll 1
    for (int rr = 0; rr < 16; rr++) {
        int i = w * 16 + rr;
        const float* srow = sc + i * SC_STR;
        __half2 h0 = __halves2half2(
            __float2half_rn(2.0f * srow[2 * lane]      - dB[2 * lane]),
            __float2half_rn(2.0f * srow[2 * lane + 1]  - dB[2 * lane + 1]));
        __half2 h1 = __halves2half2(
            __float2half_rn(2.0f * srow[2 * lane + 64] - dB[2 * lane + 64]),
            __float2half_rn(2.0f * srow[2 * lane + 65] - dB[2 * lane + 65]));
        __half2* dst = (__half2*)(G + (size_t)(by * 128 + i) * HW + bx * 128);
        dst[lane] = h0;
        dst[lane + 32] = h1;
    }
    // mirror: rows in bx-block, cols in by-block (transposed read, stride 129 => low conflict)
    if (bx != by) {
#pragma unroll 1
        for (int rr = 0; rr < 16; rr++) {
            int j = w * 16 + rr;
            __half2 h0 = __halves2half2(
                __float2half_rn(2.0f * sc[(2 * lane) * SC_STR + j]      - dA[2 * lane]),
                __float2half_rn(2.0f * sc[(2 * lane + 1) * SC_STR + j]  - dA[2 * lane + 1]));
            __half2 h1 = __halves2half2(
                __float2half_rn(2.0f * sc[(2 * lane + 64) * SC_STR + j] - dA[2 * lane + 64]),
                __float2half_rn(2.0f * sc[(2 * lane + 65) * SC_STR + j] - dA[2 * lane + 65]));
            __half2* dst = (__half2*)(G + (size_t)(bx * 128 + j) * HW + by * 128);
            dst[lane] = h0;
            dst[lane + 32] = h1;
        }
    }
}

// ---------------- 4) per-row top-16 via packed keys + REDUX ----------------
__global__ void __launch_bounds__(256) k_topk() {
    __shared__ uint32_t sc[HW];     // 16KB keys
    __shared__ uint32_t wv[2][8];
    __shared__ uint32_t bc[2];
    int mod = blockIdx.z, n = blockIdx.y, i = blockIdx.x;
    int t = threadIdx.x, w = t >> 5, l = t & 31;
    const uint32_t* S = (const uint32_t*)(g_scoresh[mod]
                         + (size_t)n * HW * HW + (size_t)i * HW);

    uint32_t myKey = 0;
#pragma unroll
    for (int step = 0; step < 8; step++) {
        int j = 2 * t + 512 * step;
        uint32_t pk = S[j >> 1];
        uint32_t h0 = pk & 0xFFFFu, h1 = pk >> 16;
        uint32_t o0 = (h0 & 0x8000u) ? (~h0 & 0xFFFFu) : (h0 | 0x8000u);
        uint32_t o1 = (h1 & 0x8000u) ? (~h1 & 0xFFFFu) : (h1 | 0x8000u);
        uint32_t k0 = (o0 << 12) | (uint32_t)(4095 - j);
        uint32_t k1 = (o1 << 12) | (uint32_t)(4094 - j);
        sc[j] = k0; sc[j + 1] = k1;
        myKey = max(myKey, max(k0, k1));
    }
    __syncthreads();

    int* out = g_knn[mod] + ((size_t)n * HW + i) * KNN;
#pragma unroll 1
    for (int s = 0; s < KNN; s++) {
        int pb = s & 1;
        uint32_t wk = __reduce_max_sync(0xffffffffu, myKey);
        if (l == 0) wv[pb][w] = wk;
        __syncthreads();
        if (t == 0) {
            uint32_t B = wv[pb][0];
#pragma unroll
            for (int u = 1; u < 8; u++) B = max(B, wv[pb][u]);
            bc[pb] = B;
            out[s] = 4095 - (int)(B & 0xFFFu);
        }
        __syncthreads();
        uint32_t best = bc[pb];
        if (myKey == best) {
            int jwin = 4095 - (int)(best & 0xFFFu);
            sc[jwin] = 0;
            uint32_t nk = 0;
#pragma unroll
            for (int step = 0; step < 8; step++) {
                int j = 2 * t + 512 * step;
                nk = max(nk, max(sc[j], sc[j + 1]));
            }
            myKey = nk;
        }
    }
}

// ---------------- 5) A/B tables ----------------
__global__ __launch_bounds__(256) void k_ab(const float* __restrict__ Wr,
                                            const float* __restrict__ Wi) {
    __shared__ float Xs[64][36];
    __shared__ float Ws[32][128];
    int which = blockIdx.y;
    const float* X  = (which == 0 || which == 3) ? g_xt[0] : g_xt[1];
    const float* Wg = (which < 2) ? Wr : Wi;
    bool both = (which == 0 || which == 2);
    int r0 = blockIdx.x * 64;
    int tx = threadIdx.x & 15, ty = threadIdx.x >> 4;

    float acc[4][8];
#pragma unroll
    for (int i = 0; i < 4; i++)
#pragma unroll
        for (int j = 0; j < 8; j++) acc[i][j] = 0.0f;

    for (int k0 = 0; k0 < 128; k0 += 32) {
#pragma unroll
        for (int p = 0; p < 2; p++) {
            int f4 = threadIdx.x + 256 * p;
            int r = f4 >> 3, kq = f4 & 7;
            *(float4*)(&Xs[r][kq * 4]) =
                *(const float4*)(X + (size_t)(r0 + r) * CCH + k0 + kq * 4);
        }
#pragma unroll
        for (int p = 0; p < 4; p++) {
            int f4 = threadIdx.x + 256 * p;
            int kk = f4 >> 5, cq = f4 & 31;
            float4 w = *(const float4*)(Wg + (size_t)(128 + k0 + kk) * CCH + cq * 4);
            if (both) {
                float4 w0 = *(const float4*)(Wg + (size_t)(k0 + kk) * CCH + cq * 4);
                w.x += w0.x; w.y += w0.y; w.z += w0.z; w.w += w0.w;
            }
            *(float4*)(&Ws[kk][cq * 4]) = w;
        }
        __syncthreads();
#pragma unroll 8
        for (int kk = 0; kk < 32; kk++) {
            float a[4], b[8];
#pragma unroll
            for (int i = 0; i < 4; i++) a[i] = Xs[ty + 16 * i][kk];
#pragma unroll
            for (int j = 0; j < 8; j++) b[j] = Ws[kk][tx + 16 * j];
#pragma unroll
            for (int i = 0; i < 4; i++)
#pragma unroll
                for (int j = 0; j < 8; j++) acc[i][j] += a[i] * b[j];
        }
        __syncthreads();
    }
#pragma unroll
    for (int i = 0; i < 4; i++)
#pragma unroll
        for (int j = 0; j < 8; j++)
            g_AB[which][(size_t)(r0 + ty + 16 * i) * CCH + tx + 16 * j] = acc[i][j];
}

// ---------------- 6) pair gather-mean ----------------
__global__ __launch_bounds__(128) void k_pair(const float* __restrict__ br,
                                              const float* __restrict__ bi) {
    __shared__ int sp[256], sq[256];
    int n = blockIdx.y;
    int base = n * PAIRS + blockIdx.x * 256;
    for (int t = threadIdx.x; t < 256; t += 128) {
        sp[t] = g_knn[0][base + t];
        sq[t] = g_knn[1][base + t];
    }
    __syncthreads();
    int c = threadIdx.x;
    float brc = br[c], bic = bi[c];
    float aR = 0.0f, aI = 0.0f;
#pragma unroll 4
    for (int t = 0; t < 256; t++) {
        int p = sp[t], q = sq[t];
        float fr = g_AB[0][p * CCH + c] - g_AB[1][q * CCH + c] + brc;
        aR += (fr >= 0.0f) ? fr : 0.01f * fr;
        float fi = g_AB[2][q * CCH + c] - g_AB[3][p * CCH + c] + bic;
        aI += (fi >= 0.0f) ? fi : 0.01f * fi;
    }
    int b = n * 256 + blockIdx.x;
    g_partial[b][c]       = aR;
    g_partial[b][c + 128] = aI;
}

// ---------------- 7) reduce -> m ----------------
__global__ void k_reduce_m() {
    int n = blockIdx.x, d = threadIdx.x;
    float s = 0.0f;
    for (int bb = 0; bb < 256; bb++) s += g_partial[n * 256 + bb][d];
    g_m[n * 256 + d] = s * (1.0f / (float)PAIRS);
}

// ---------------- 8) SE gate ----------------
__global__ void k_se(const float* __restrict__ w1, const float* __restrict__ b1,
                     const float* __restrict__ w2, const float* __restrict__ b2) {
    __shared__ float tm[NB][8];
    int tid = threadIdx.x;
    if (tid < 32) {
        int n = tid >> 3, j = tid & 7;
        float s = b1[j];
        for (int d = 0; d < 256; d++) s += g_m[n * 256 + d] * w1[d * 8 + j];
        tm[n][j] = (s >= 0.0f) ? s : 0.01f * s;
    }
    __syncthreads();
    int n = tid >> 7, c = tid & 127;
    float s = b2[c];
#pragma unroll
    for (int j = 0; j < 8; j++) s += tm[n][j] * w2[j * 128 + c];
    g_gate[n * 128 + c] = 1.0f / (1.0f + expf(-s));
}

// ---------------- 9) gated blend + relu ----------------
__global__ void k_out(const float* __restrict__ g1, const float* __restrict__ g2,
                      float* __restrict__ out) {
    int o = blockIdx.x * blockDim.x + threadIdx.x;
    if (o >= NB * CCH * HW) return;
    int nc = o >> 12;
    float g = g_gate[nc];
    float v = g1[0] * g * g_pool[0][o] + g2[0] * (1.0f - g) * g_pool[1][o];
    out[o] = fmaxf(v, 0.0f);
}

// ---------------- launch ----------------
extern "C" void kernel_launch(void* const* d_in, const int* in_sizes, int n_in,
                              void* d_out, int out_size) {
    const float* rgb = (const float*)d_in[0];
    const float* ir  = (const float*)d_in[1];
    const float* Wr  = (const float*)d_in[2];
    const float* br  = (const float*)d_in[3];
    const float* Wi  = (const float*)d_in[4];
    const float* bi  = (const float*)d_in[5];
    const float* w1  = (const float*)d_in[6];
    const float* b1  = (const float*)d_in[7];
    const float* w2  = (const float*)d_in[8];
    const float* b2  = (const float*)d_in[9];
    const float* g1  = (const float*)d_in[10];
    const float* g2  = (const float*)d_in[11];
    float* out = (float*)d_out;

    cudaFuncSetAttribute(k_gram_tri, cudaFuncAttributeMaxDynamicSharedMemorySize, GS_TOTAL);

    k_pool<<<8192, 256>>>(rgb, ir);
    k_tnorm<<<dim3(128, 4, 2), 256>>>();
    k_ab<<<dim3(64, 4), 256>>>(Wr, Wi);

    k_gram_tri<<<dim3(528, 8), 256, GS_TOTAL>>>();   // triangular: direct + mirror scores
    k_topk<<<dim3(4096, 4, 2), 256>>>();             // packed-key REDUX top-16

    k_pair<<<dim3(256, 4), 128>>>(br, bi);
    k_reduce_m<<<4, 256>>>();
    k_se<<<1, 512>>>(w1, b1, w2, b2);
    k_out<<<8192, 256>>>(g1, g2, out);
}

// round 11
// speedup vs baseline: 6.3122x; 1.0455x over previous
#include <cuda_runtime.h>
#include <cuda_bf16.h>
#include <cuda_fp16.h>
#include <math.h>
#include <stdint.h>

#define NB    4
#define CCH   128
#define HW    4096            // 64*64 after 2x2 pool
#define KNN   16
#define PAIRS 65536           // HW*KNN per batch
#define NEGINF (-3.4e38f)

// ======================= helpers =======================
__device__ __forceinline__ uint32_t smem_u32(const void* p) {
    uint32_t a;
    asm("{ .reg .u64 t; cvta.to.shared.u64 t, %1; cvt.u32.u64 %0, t; }" : "=r"(a) : "l"(p));
    return a;
}
__device__ __forceinline__ void ldm_x4(uint32_t* r, uint32_t a) {
    asm volatile("ldmatrix.sync.aligned.m8n8.x4.shared.b16 {%0,%1,%2,%3}, [%4];"
        : "=r"(r[0]), "=r"(r[1]), "=r"(r[2]), "=r"(r[3]) : "r"(a));
}
__device__ __forceinline__ void mma_bf16(float* c, const uint32_t* a, const uint32_t* b) {
    asm volatile("mma.sync.aligned.m16n8k16.row.col.f32.bf16.bf16.f32 "
        "{%0,%1,%2,%3}, {%4,%5,%6,%7}, {%8,%9}, {%0,%1,%2,%3};"
        : "+f"(c[0]), "+f"(c[1]), "+f"(c[2]), "+f"(c[3])
        : "r"(a[0]), "r"(a[1]), "r"(a[2]), "r"(a[3]), "r"(b[0]), "r"(b[1]));
}

// ======================= scratch (device globals) =======================
__device__ __align__(16) float g_pool[2][NB * CCH * HW];
__device__ __align__(16) float g_xt  [2][HW * CCH];                 // batch 0 only
__device__ __align__(16) __nv_bfloat16 g_xh[2][NB * HW * CCH];
__device__ __align__(16) float g_diag[2][NB * HW];
__device__ __align__(16) __half g_scoresh[2][(size_t)NB * HW * HW]; // 2 x 128MB
__device__              int   g_knn [2][NB * PAIRS];
__device__ __align__(16) float g_AB  [4][HW * CCH];
__device__ __align__(16) float g_partial[1024][256];
__device__ __align__(16) float g_m   [NB * 256];
__device__ __align__(16) float g_gate[NB * CCH];

// ---------------- 1) maxpool 2x2 ----------------
__global__ void k_pool(const float* __restrict__ rgb, const float* __restrict__ ir) {
    int o = blockIdx.x * blockDim.x + threadIdx.x;
    if (o >= NB * CCH * HW) return;
    int x  = o & 63;
    int y  = (o >> 6) & 63;
    int nc = o >> 12;
    int ib = nc * (128 * 128) + (2 * y) * 128 + 2 * x;
    {
        float a = rgb[ib], b = rgb[ib + 1], c = rgb[ib + 128], d = rgb[ib + 129];
        g_pool[0][o] = fmaxf(fmaxf(a, b), fmaxf(c, d));
    }
    {
        float a = ir[ib], b = ir[ib + 1], c = ir[ib + 128], d = ir[ib + 129];
        g_pool[1][o] = fmaxf(fmaxf(a, b), fmaxf(c, d));
    }
}

// ---------------- 2) fused transpose + normalize -> bf16 xh, diag, xt(batch0) ----------------
__global__ void __launch_bounds__(256) k_tnorm() {
    __shared__ float s[128][33];
    int mod = blockIdx.z, n = blockIdx.y, hw0 = blockIdx.x * 32;
    const float* src = g_pool[mod] + (size_t)n * CCH * HW + hw0;
#pragma unroll
    for (int p = 0; p < 16; p++) {
        int i = threadIdx.x + 256 * p;      // 128c x 32hw
        int c = i >> 5, hl = i & 31;
        s[c][hl] = src[(size_t)c * HW + hl];
    }
    __syncthreads();
    int w = threadIdx.x >> 5, l = threadIdx.x & 31;
#pragma unroll
    for (int m = 0; m < 4; m++) {
        int hw = w * 4 + m;
        float a0 = s[l][hw], a1 = s[l + 32][hw], a2 = s[l + 64][hw], a3 = s[l + 96][hw];
        float ss = a0 * a0 + a1 * a1 + a2 * a2 + a3 * a3;
#pragma unroll
        for (int off = 16; off > 0; off >>= 1) ss += __shfl_xor_sync(0xffffffff, ss, off);
        float inv = 1.0f / fmaxf(sqrtf(ss), 1e-12f);
        union { __nv_bfloat16 b[2]; uint32_t u; } w0, w1;
        w0.b[0] = __float2bfloat16_rn(s[2 * l][hw] * inv);
        w0.b[1] = __float2bfloat16_rn(s[2 * l + 1][hw] * inv);
        w1.b[0] = __float2bfloat16_rn(s[2 * l + 64][hw] * inv);
        w1.b[1] = __float2bfloat16_rn(s[2 * l + 65][hw] * inv);
        uint32_t* dst = (uint32_t*)(g_xh[mod] + (size_t)(n * HW + hw0 + hw) * CCH);
        dst[l] = w0.u;
        dst[l + 32] = w1.u;
        if (n == 0) {
            float* xd = g_xt[mod] + (size_t)(hw0 + hw) * CCH;
            xd[l] = a0; xd[l + 32] = a1; xd[l + 64] = a2; xd[l + 96] = a3;
        }
        if (l == 0) g_diag[mod][n * HW + hw0 + hw] = ss * inv * inv;
    }
}

// ---------------- 3) triangular bf16 gram -> fp16 scores (direct + mirror) ----------------
#define TILE_STRIDE_B 272                 // 136 bf16 * 2
#define TILE_BYTES    (128 * TILE_STRIDE_B)
#define GS_DIAGA 0
#define GS_DIAGB 512
#define GS_AH    1024
#define GS_BH    (GS_AH + TILE_BYTES)
#define GS_SC    1024                     // fp16 overlay 128 x 130 halves = 33280 B
#define SC_STR   130
#define GS_TOTAL (GS_AH + 2 * TILE_BYTES)   // 70656 B

__global__ void __launch_bounds__(256, 2) k_gram_tri() {
    extern __shared__ char smem[];
    uint32_t sb = smem_u32(smem);
    int tid = threadIdx.x, lane = tid & 31, w = tid >> 5;
    int t = blockIdx.x;
    int mod = blockIdx.y >> 2, n = blockIdx.y & 3;

    int by = (int)((sqrtf(8.0f * t + 1.0f) - 1.0f) * 0.5f);
    while ((by + 1) * (by + 2) / 2 <= t) by++;
    while (by * (by + 1) / 2 > t) by--;
    int bx = t - by * (by + 1) / 2;       // bx <= by

    const __nv_bfloat16* XH = g_xh[mod];
    int rowA0 = n * HW + by * 128;
    int rowB0 = n * HW + bx * 128;

    for (int i = tid; i < 2048; i += 256) {
        int r = i >> 4, ch = i & 15;
        uint32_t so = (uint32_t)r * TILE_STRIDE_B + (uint32_t)ch * 16u;
        *(uint4*)(smem + GS_AH + so) = *((const uint4*)(XH + (size_t)(rowA0 + r) * CCH) + ch);
        *(uint4*)(smem + GS_BH + so) = *((const uint4*)(XH + (size_t)(rowB0 + r) * CCH) + ch);
    }
    if (tid < 128)      ((float*)(smem + GS_DIAGA))[tid] = g_diag[mod][n * HW + by * 128 + tid];
    else                ((float*)(smem + GS_DIAGB))[tid - 128] =
                            g_diag[mod][n * HW + bx * 128 + (tid - 128)];
    __syncthreads();

    int wm = w >> 1, wn = w & 1;
    int m_base = wm * 32, n_base = wn * 64;

    float acc[2][8][4];
#pragma unroll
    for (int mf = 0; mf < 2; mf++)
#pragma unroll
        for (int nf = 0; nf < 8; nf++)
#pragma unroll
            for (int q = 0; q < 4; q++) acc[mf][nf][q] = 0.0f;

    int arow  = lane & 15;
    int acol8 = (lane >> 4) << 3;
    int brow  = ((lane >> 4) << 3) + (lane & 7);
    int bcol8 = ((lane >> 3) & 1) << 3;

    uint32_t aaddr = sb + GS_AH + (uint32_t)(m_base + arow) * TILE_STRIDE_B + (uint32_t)acol8 * 2u;
    uint32_t baddr = sb + GS_BH + (uint32_t)(n_base + brow) * TILE_STRIDE_B + (uint32_t)bcol8 * 2u;

#pragma unroll 2
    for (int k0 = 0; k0 < 128; k0 += 16) {
        uint32_t a[2][4], b[4][4];
        ldm_x4(a[0], aaddr + (uint32_t)k0 * 2u);
        ldm_x4(a[1], aaddr + 16u * TILE_STRIDE_B + (uint32_t)k0 * 2u);
#pragma unroll
        for (int q = 0; q < 4; q++)
            ldm_x4(b[q], baddr + (uint32_t)(q * 16) * TILE_STRIDE_B + (uint32_t)k0 * 2u);
#pragma unroll
        for (int mf = 0; mf < 2; mf++)
#pragma unroll
            for (int nf = 0; nf < 8; nf++)
                mma_bf16(acc[mf][nf], a[mf], &b[nf >> 1][(nf & 1) * 2]);
    }

    __syncthreads();   // operands dead; overlay with raw g (fp16)

    {
        __half* sch = (__half*)(smem + GS_SC);
        int r_in  = lane >> 2;
        int cpair = (lane & 3) * 2;
#pragma unroll
        for (int mf = 0; mf < 2; mf++) {
            int rl = m_base + mf * 16 + r_in;
#pragma unroll
            for (int nf = 0; nf < 8; nf++) {
                int col = n_base + nf * 8 + cpair;
                *(__half2*)(sch + rl * SC_STR + col) =
                    __floats2half2_rn(acc[mf][nf][0], acc[mf][nf][1]);
                *(__half2*)(sch + (rl + 8) * SC_STR + col) =
                    __floats2half2_rn(acc[mf][nf][2], acc[mf][nf][3]);
            }
        }
    }
    __syncthreads();

    const __half* sch = (const __half*)(smem + GS_SC);
    const float* dA = (const float*)(smem + GS_DIAGA);
    const float* dB = (const float*)(smem + GS_DIAGB);
    __half* G = g_scoresh[mod] + (size_t)n * HW * HW;

    // direct: rows in by-block, cols in bx-block (row-major half2 reads, conflict-free)
#pragma unroll 1
    for (int rr = 0; rr < 16; rr++) {
        int i = w * 16 + rr;
        float2 f0 = __half22float2(*(const __half2*)(sch + i * SC_STR + 2 * lane));
        float2 f1 = __half22float2(*(const __half2*)(sch + i * SC_STR + 2 * lane + 64));
        __half2 h0 = __floats2half2_rn(2.0f * f0.x - dB[2 * lane],
                                       2.0f * f0.y - dB[2 * lane + 1]);
        __half2 h1 = __floats2half2_rn(2.0f * f1.x - dB[2 * lane + 64],
                                       2.0f * f1.y - dB[2 * lane + 65]);
        __half2* dst = (__half2*)(G + (size_t)(by * 128 + i) * HW + bx * 128);
        dst[lane] = h0;
        dst[lane + 32] = h1;
    }
    // mirror: column-pair reads cover two output rows per iteration
    if (bx != by) {
#pragma unroll 1
        for (int p = 0; p < 8; p++) {
            int j = w * 16 + 2 * p;
            float2 ga = __half22float2(*(const __half2*)(sch + (2 * lane) * SC_STR + j));
            float2 gb = __half22float2(*(const __half2*)(sch + (2 * lane + 1) * SC_STR + j));
            float2 gc = __half22float2(*(const __half2*)(sch + (2 * lane + 64) * SC_STR + j));
            float2 gd = __half22float2(*(const __half2*)(sch + (2 * lane + 65) * SC_STR + j));
            float da0 = dA[2 * lane], da1 = dA[2 * lane + 1];
            float da2 = dA[2 * lane + 64], da3 = dA[2 * lane + 65];
            __half2 r0 = __floats2half2_rn(2.0f * ga.x - da0, 2.0f * gb.x - da1);
            __half2 r1 = __floats2half2_rn(2.0f * gc.x - da2, 2.0f * gd.x - da3);
            __half2* d0 = (__half2*)(G + (size_t)(bx * 128 + j) * HW + by * 128);
            d0[lane] = r0;
            d0[lane + 32] = r1;
            __half2 s0 = __floats2half2_rn(2.0f * ga.y - da0, 2.0f * gb.y - da1);
            __half2 s1 = __floats2half2_rn(2.0f * gc.y - da2, 2.0f * gd.y - da3);
            __half2* d1 = (__half2*)(G + (size_t)(bx * 128 + j + 1) * HW + by * 128);
            d1[lane] = s0;
            d1[lane + 32] = s1;
        }
    }
}

// ---------------- 4) per-row top-16 via packed keys + REDUX ----------------
// key = (ordered_fp16 << 12) | (4095 - j): u32 max == (max score, min index)
__global__ void __launch_bounds__(256) k_topk() {
    __shared__ uint32_t sc[HW];     // 16KB keys
    __shared__ uint32_t wv[2][8];
    __shared__ uint32_t bc[2];
    int mod = blockIdx.z, n = blockIdx.y, i = blockIdx.x;
    int t = threadIdx.x, w = t >> 5, l = t & 31;
    const uint4* S4 = (const uint4*)(g_scoresh[mod]
                        + (size_t)n * HW * HW + (size_t)i * HW);

    uint32_t myKey = 0;
#pragma unroll
    for (int step = 0; step < 2; step++) {
        int v = t + 256 * step;
        uint4 pk = S4[v];
        int j0 = v * 8;
        uint32_t pw[4] = { pk.x, pk.y, pk.z, pk.w };
#pragma unroll
        for (int q = 0; q < 4; q++) {
            int j = j0 + 2 * q;
            uint32_t h0 = pw[q] & 0xFFFFu, h1 = pw[q] >> 16;
            uint32_t o0 = (h0 & 0x8000u) ? (~h0 & 0xFFFFu) : (h0 | 0x8000u);
            uint32_t o1 = (h1 & 0x8000u) ? (~h1 & 0xFFFFu) : (h1 | 0x8000u);
            uint32_t k0 = (o0 << 12) | (uint32_t)(4095 - j);
            uint32_t k1 = (o1 << 12) | (uint32_t)(4094 - j);
            sc[j] = k0; sc[j + 1] = k1;
            myKey = max(myKey, max(k0, k1));
        }
    }
    __syncthreads();

    int* out = g_knn[mod] + ((size_t)n * HW + i) * KNN;
#pragma unroll 1
    for (int s = 0; s < KNN; s++) {
        int pb = s & 1;
        uint32_t wk = __reduce_max_sync(0xffffffffu, myKey);
        if (l == 0) wv[pb][w] = wk;
        __syncthreads();
        if (t == 0) {
            uint32_t B = wv[pb][0];
#pragma unroll
            for (int u = 1; u < 8; u++) B = max(B, wv[pb][u]);
            bc[pb] = B;
            out[s] = 4095 - (int)(B & 0xFFFu);
        }
        __syncthreads();
        uint32_t best = bc[pb];
        if (myKey == best) {   // unique owner (index embedded in key)
            int jwin = 4095 - (int)(best & 0xFFFu);
            sc[jwin] = 0;
            uint32_t nk = 0;
#pragma unroll
            for (int q = 0; q < 8; q++)
                nk = max(nk, max(sc[8 * t + q], sc[2048 + 8 * t + q]));
            myKey = nk;
        }
    }
}

// ---------------- 5) A/B tables ----------------
__global__ __launch_bounds__(256) void k_ab(const float* __restrict__ Wr,
                                            const float* __restrict__ Wi) {
    __shared__ float Xs[64][36];
    __shared__ float Ws[32][128];
    int which = blockIdx.y;
    const float* X  = (which == 0 || which == 3) ? g_xt[0] : g_xt[1];
    const float* Wg = (which < 2) ? Wr : Wi;
    bool both = (which == 0 || which == 2);
    int r0 = blockIdx.x * 64;
    int tx = threadIdx.x & 15, ty = threadIdx.x >> 4;

    float acc[4][8];
#pragma unroll
    for (int i = 0; i < 4; i++)
#pragma unroll
        for (int j = 0; j < 8; j++) acc[i][j] = 0.0f;

    for (int k0 = 0; k0 < 128; k0 += 32) {
#pragma unroll
        for (int p = 0; p < 2; p++) {
            int f4 = threadIdx.x + 256 * p;
            int r = f4 >> 3, kq = f4 & 7;
            *(float4*)(&Xs[r][kq * 4]) =
                *(const float4*)(X + (size_t)(r0 + r) * CCH + k0 + kq * 4);
        }
#pragma unroll
        for (int p = 0; p < 4; p++) {
            int f4 = threadIdx.x + 256 * p;
            int kk = f4 >> 5, cq = f4 & 31;
            float4 w = *(const float4*)(Wg + (size_t)(128 + k0 + kk) * CCH + cq * 4);
            if (both) {
                float4 w0 = *(const float4*)(Wg + (size_t)(k0 + kk) * CCH + cq * 4);
                w.x += w0.x; w.y += w0.y; w.z += w0.z; w.w += w0.w;
            }
            *(float4*)(&Ws[kk][cq * 4]) = w;
        }
        __syncthreads();
#pragma unroll 8
        for (int kk = 0; kk < 32; kk++) {
            float a[4], b[8];
#pragma unroll
            for (int i = 0; i < 4; i++) a[i] = Xs[ty + 16 * i][kk];
#pragma unroll
            for (int j = 0; j < 8; j++) b[j] = Ws[kk][tx + 16 * j];
#pragma unroll
            for (int i = 0; i < 4; i++)
#pragma unroll
                for (int j = 0; j < 8; j++) acc[i][j] += a[i] * b[j];
        }
        __syncthreads();
    }
#pragma unroll
    for (int i = 0; i < 4; i++)
#pragma unroll
        for (int j = 0; j < 8; j++)
            g_AB[which][(size_t)(r0 + ty + 16 * i) * CCH + tx + 16 * j] = acc[i][j];
}

// ---------------- 6) pair gather-mean ----------------
__global__ __launch_bounds__(128) void k_pair(const float* __restrict__ br,
                                              const float* __restrict__ bi) {
    __shared__ int sp[256], sq[256];
    int n = blockIdx.y;
    int base = n * PAIRS + blockIdx.x * 256;
    for (int t = threadIdx.x; t < 256; t += 128) {
        sp[t] = g_knn[0][base + t];
        sq[t] = g_knn[1][base + t];
    }
    __syncthreads();
    int c = threadIdx.x;
    float brc = br[c], bic = bi[c];
    float aR = 0.0f, aI = 0.0f;
#pragma unroll 4
    for (int t = 0; t < 256; t++) {
        int p = sp[t], q = sq[t];
        float fr = g_AB[0][p * CCH + c] - g_AB[1][q * CCH + c] + brc;
        aR += (fr >= 0.0f) ? fr : 0.01f * fr;
        float fi = g_AB[2][q * CCH + c] - g_AB[3][p * CCH + c] + bic;
        aI += (fi >= 0.0f) ? fi : 0.01f * fi;
    }
    int b = n * 256 + blockIdx.x;
    g_partial[b][c]       = aR;
    g_partial[b][c + 128] = aI;
}

// ---------------- 7) reduce -> m ----------------
__global__ void k_reduce_m() {
    int n = blockIdx.x, d = threadIdx.x;
    float s = 0.0f;
    for (int bb = 0; bb < 256; bb++) s += g_partial[n * 256 + bb][d];
    g_m[n * 256 + d] = s * (1.0f / (float)PAIRS);
}

// ---------------- 8) SE gate ----------------
__global__ void k_se(const float* __restrict__ w1, const float* __restrict__ b1,
                     const float* __restrict__ w2, const float* __restrict__ b2) {
    __shared__ float tm[NB][8];
    int tid = threadIdx.x;
    if (tid < 32) {
        int n = tid >> 3, j = tid & 7;
        float s = b1[j];
        for (int d = 0; d < 256; d++) s += g_m[n * 256 + d] * w1[d * 8 + j];
        tm[n][j] = (s >= 0.0f) ? s : 0.01f * s;
    }
    __syncthreads();
    int n = tid >> 7, c = tid & 127;
    float s = b2[c];
#pragma unroll
    for (int j = 0; j < 8; j++) s += tm[n][j] * w2[j * 128 + c];
    g_gate[n * 128 + c] = 1.0f / (1.0f + expf(-s));
}

// ---------------- 9) gated blend + relu ----------------
__global__ void k_out(const float* __restrict__ g1, const float* __restrict__ g2,
                      float* __restrict__ out) {
    int o = blockIdx.x * blockDim.x + threadIdx.x;
    if (o >= NB * CCH * HW) return;
    int nc = o >> 12;
    float g = g_gate[nc];
    float v = g1[0] * g * g_pool[0][o] + g2[0] * (1.0f - g) * g_pool[1][o];
    out[o] = fmaxf(v, 0.0f);
}

// ---------------- launch ----------------
extern "C" void kernel_launch(void* const* d_in, const int* in_sizes, int n_in,
                              void* d_out, int out_size) {
    const float* rgb = (const float*)d_in[0];
    const float* ir  = (const float*)d_in[1];
    const float* Wr  = (const float*)d_in[2];
    const float* br  = (const float*)d_in[3];
    const float* Wi  = (const float*)d_in[4];
    const float* bi  = (const float*)d_in[5];
    const float* w1  = (const float*)d_in[6];
    const float* b1  = (const float*)d_in[7];
    const float* w2  = (const float*)d_in[8];
    const float* b2  = (const float*)d_in[9];
    const float* g1  = (const float*)d_in[10];
    const float* g2  = (const float*)d_in[11];
    float* out = (float*)d_out;

    cudaFuncSetAttribute(k_gram_tri, cudaFuncAttributeMaxDynamicSharedMemorySize, GS_TOTAL);

    k_pool<<<8192, 256>>>(rgb, ir);
    k_tnorm<<<dim3(128, 4, 2), 256>>>();
    k_ab<<<dim3(64, 4), 256>>>(Wr, Wi);

    k_gram_tri<<<dim3(528, 8), 256, GS_TOTAL>>>();   // triangular, fp16 overlay epilogue
    k_topk<<<dim3(4096, 4, 2), 256>>>();             // packed-key REDUX top-16

    k_pair<<<dim3(256, 4), 128>>>(br, bi);
    k_reduce_m<<<4, 256>>>();
    k_se<<<1, 512>>>(w1, b1, w2, b2);
    k_out<<<8192, 256>>>(g1, g2, out);
}

// round 12
// speedup vs baseline: 6.5446x; 1.0368x over previous
#include <cuda_runtime.h>
#include <cuda_bf16.h>
#include <cuda_fp16.h>
#include <math.h>
#include <stdint.h>

#define NB    4
#define CCH   128
#define HW    4096            // 64*64 after 2x2 pool
#define KNN   16
#define PAIRS 65536           // HW*KNN per batch
#define NEGINF (-3.4e38f)

// ======================= helpers =======================
__device__ __forceinline__ uint32_t smem_u32(const void* p) {
    uint32_t a;
    asm("{ .reg .u64 t; cvta.to.shared.u64 t, %1; cvt.u32.u64 %0, t; }" : "=r"(a) : "l"(p));
    return a;
}
__device__ __forceinline__ void ldm_x4(uint32_t* r, uint32_t a) {
    asm volatile("ldmatrix.sync.aligned.m8n8.x4.shared.b16 {%0,%1,%2,%3}, [%4];"
        : "=r"(r[0]), "=r"(r[1]), "=r"(r[2]), "=r"(r[3]) : "r"(a));
}
__device__ __forceinline__ void mma_bf16(float* c, const uint32_t* a, const uint32_t* b) {
    asm volatile("mma.sync.aligned.m16n8k16.row.col.f32.bf16.bf16.f32 "
        "{%0,%1,%2,%3}, {%4,%5,%6,%7}, {%8,%9}, {%0,%1,%2,%3};"
        : "+f"(c[0]), "+f"(c[1]), "+f"(c[2]), "+f"(c[3])
        : "r"(a[0]), "r"(a[1]), "r"(a[2]), "r"(a[3]), "r"(b[0]), "r"(b[1]));
}

// ======================= scratch (device globals) =======================
__device__ __align__(16) float g_pool[2][NB * CCH * HW];
__device__ __align__(16) float g_xt  [2][HW * CCH];                 // batch 0 only
__device__ __align__(16) __nv_bfloat16 g_xh[2][NB * HW * CCH];
__device__ __align__(16) float g_diag[2][NB * HW];
__device__ __align__(16) __half g_scoresh[2][(size_t)NB * HW * HW]; // 2 x 128MB
__device__              int   g_knn [2][NB * PAIRS];
__device__ __align__(16) float g_AB  [4][HW * CCH];
__device__ __align__(16) float g_partial[1024][256];
__device__ __align__(16) float g_p2[64][256];
__device__ __align__(16) float g_gate[NB * CCH];

// ---------------- 1) fused maxpool + transpose + normalize ----------------
__global__ void __launch_bounds__(256) k_tnorm(const float* __restrict__ rgb,
                                               const float* __restrict__ ir) {
    __shared__ float s[128][33];
    int mod = blockIdx.z, n = blockIdx.y, hw0 = blockIdx.x * 32;
    const float* src = (mod == 0) ? rgb : ir;
    int y = hw0 >> 6, x0 = hw0 & 63;
    float* pooldst = g_pool[mod] + (size_t)n * CCH * HW;
#pragma unroll
    for (int p = 0; p < 16; p++) {
        int i = threadIdx.x + 256 * p;      // 128c x 32x
        int c = i >> 5, xl = i & 31;
        size_t base = ((size_t)(n * CCH + c) * 128 + 2 * y) * 128 + 2 * (x0 + xl);
        float2 u = *(const float2*)(src + base);
        float2 v = *(const float2*)(src + base + 128);
        float pv = fmaxf(fmaxf(u.x, u.y), fmaxf(v.x, v.y));
        s[c][xl] = pv;
        pooldst[(size_t)c * HW + hw0 + xl] = pv;
    }
    __syncthreads();
    int w = threadIdx.x >> 5, l = threadIdx.x & 31;
#pragma unroll
    for (int m = 0; m < 4; m++) {
        int hw = w * 4 + m;
        float a0 = s[l][hw], a1 = s[l + 32][hw], a2 = s[l + 64][hw], a3 = s[l + 96][hw];
        float ss = a0 * a0 + a1 * a1 + a2 * a2 + a3 * a3;
#pragma unroll
        for (int off = 16; off > 0; off >>= 1) ss += __shfl_xor_sync(0xffffffff, ss, off);
        float inv = 1.0f / fmaxf(sqrtf(ss), 1e-12f);
        union { __nv_bfloat16 b[2]; uint32_t u; } w0, w1;
        w0.b[0] = __float2bfloat16_rn(s[2 * l][hw] * inv);
        w0.b[1] = __float2bfloat16_rn(s[2 * l + 1][hw] * inv);
        w1.b[0] = __float2bfloat16_rn(s[2 * l + 64][hw] * inv);
        w1.b[1] = __float2bfloat16_rn(s[2 * l + 65][hw] * inv);
        uint32_t* dst = (uint32_t*)(g_xh[mod] + (size_t)(n * HW + hw0 + hw) * CCH);
        dst[l] = w0.u;
        dst[l + 32] = w1.u;
        if (n == 0) {
            float* xd = g_xt[mod] + (size_t)(hw0 + hw) * CCH;
            xd[l] = a0; xd[l + 32] = a1; xd[l + 64] = a2; xd[l + 96] = a3;
        }
        if (l == 0) g_diag[mod][n * HW + hw0 + hw] = ss * inv * inv;
    }
}

// ---------------- 2) triangular bf16 gram -> fp16 scores (direct + mirror) ----------------
#define TILE_STRIDE_B 272                 // 136 bf16 * 2
#define TILE_BYTES    (128 * TILE_STRIDE_B)
#define GS_DIAGA 0
#define GS_DIAGB 512
#define GS_AH    1024
#define GS_BH    (GS_AH + TILE_BYTES)
#define GS_SC    1024                     // fp16 overlay 128 x 130 halves = 33280 B
#define SC_STR   130
#define GS_TOTAL (GS_AH + 2 * TILE_BYTES)   // 70656 B

__global__ void __launch_bounds__(256, 2) k_gram_tri() {
    extern __shared__ char smem[];
    uint32_t sb = smem_u32(smem);
    int tid = threadIdx.x, lane = tid & 31, w = tid >> 5;
    int t = blockIdx.x;
    int mod = blockIdx.y >> 2, n = blockIdx.y & 3;

    int by = (int)((sqrtf(8.0f * t + 1.0f) - 1.0f) * 0.5f);
    while ((by + 1) * (by + 2) / 2 <= t) by++;
    while (by * (by + 1) / 2 > t) by--;
    int bx = t - by * (by + 1) / 2;       // bx <= by

    const __nv_bfloat16* XH = g_xh[mod];
    int rowA0 = n * HW + by * 128;
    int rowB0 = n * HW + bx * 128;

    for (int i = tid; i < 2048; i += 256) {
        int r = i >> 4, ch = i & 15;
        uint32_t so = (uint32_t)r * TILE_STRIDE_B + (uint32_t)ch * 16u;
        *(uint4*)(smem + GS_AH + so) = *((const uint4*)(XH + (size_t)(rowA0 + r) * CCH) + ch);
        *(uint4*)(smem + GS_BH + so) = *((const uint4*)(XH + (size_t)(rowB0 + r) * CCH) + ch);
    }
    if (tid < 128)      ((float*)(smem + GS_DIAGA))[tid] = g_diag[mod][n * HW + by * 128 + tid];
    else                ((float*)(smem + GS_DIAGB))[tid - 128] =
                            g_diag[mod][n * HW + bx * 128 + (tid - 128)];
    __syncthreads();

    int wm = w >> 1, wn = w & 1;
    int m_base = wm * 32, n_base = wn * 64;

    float acc[2][8][4];
#pragma unroll
    for (int mf = 0; mf < 2; mf++)
#pragma unroll
        for (int nf = 0; nf < 8; nf++)
#pragma unroll
            for (int q = 0; q < 4; q++) acc[mf][nf][q] = 0.0f;

    int arow  = lane & 15;
    int acol8 = (lane >> 4) << 3;
    int brow  = ((lane >> 4) << 3) + (lane & 7);
    int bcol8 = ((lane >> 3) & 1) << 3;

    uint32_t aaddr = sb + GS_AH + (uint32_t)(m_base + arow) * TILE_STRIDE_B + (uint32_t)acol8 * 2u;
    uint32_t baddr = sb + GS_BH + (uint32_t)(n_base + brow) * TILE_STRIDE_B + (uint32_t)bcol8 * 2u;

#pragma unroll
    for (int k0 = 0; k0 < 128; k0 += 16) {
        uint32_t a[2][4], b[4][4];
        ldm_x4(a[0], aaddr + (uint32_t)k0 * 2u);
        ldm_x4(a[1], aaddr + 16u * TILE_STRIDE_B + (uint32_t)k0 * 2u);
#pragma unroll
        for (int q = 0; q < 4; q++)
            ldm_x4(b[q], baddr + (uint32_t)(q * 16) * TILE_STRIDE_B + (uint32_t)k0 * 2u);
#pragma unroll
        for (int mf = 0; mf < 2; mf++)
#pragma unroll
            for (int nf = 0; nf < 8; nf++)
                mma_bf16(acc[mf][nf], a[mf], &b[nf >> 1][(nf & 1) * 2]);
    }

    __syncthreads();   // operands dead; overlay with raw g (fp16)

    {
        __half* sch = (__half*)(smem + GS_SC);
        int r_in  = lane >> 2;
        int cpair = (lane & 3) * 2;
#pragma unroll
        for (int mf = 0; mf < 2; mf++) {
            int rl = m_base + mf * 16 + r_in;
#pragma unroll
            for (int nf = 0; nf < 8; nf++) {
                int col = n_base + nf * 8 + cpair;
                *(__half2*)(sch + rl * SC_STR + col) =
                    __floats2half2_rn(acc[mf][nf][0], acc[mf][nf][1]);
                *(__half2*)(sch + (rl + 8) * SC_STR + col) =
                    __floats2half2_rn(acc[mf][nf][2], acc[mf][nf][3]);
            }
        }
    }
    __syncthreads();

    const __half* sch = (const __half*)(smem + GS_SC);
    const float* dA = (const float*)(smem + GS_DIAGA);
    const float* dB = (const float*)(smem + GS_DIAGB);
    __half* G = g_scoresh[mod] + (size_t)n * HW * HW;

    // direct: rows in by-block, cols in bx-block
#pragma unroll 1
    for (int rr = 0; rr < 16; rr++) {
        int i = w * 16 + rr;
        float2 f0 = __half22float2(*(const __half2*)(sch + i * SC_STR + 2 * lane));
        float2 f1 = __half22float2(*(const __half2*)(sch + i * SC_STR + 2 * lane + 64));
        __half2 h0 = __floats2half2_rn(2.0f * f0.x - dB[2 * lane],
                                       2.0f * f0.y - dB[2 * lane + 1]);
        __half2 h1 = __floats2half2_rn(2.0f * f1.x - dB[2 * lane + 64],
                                       2.0f * f1.y - dB[2 * lane + 65]);
        __half2* dst = (__half2*)(G + (size_t)(by * 128 + i) * HW + bx * 128);
        dst[lane] = h0;
        dst[lane + 32] = h1;
    }
    // mirror: column-pair reads cover two output rows per iteration
    if (bx != by) {
#pragma unroll 1
        for (int p = 0; p < 8; p++) {
            int j = w * 16 + 2 * p;
            float2 ga = __half22float2(*(const __half2*)(sch + (2 * lane) * SC_STR + j));
            float2 gb = __half22float2(*(const __half2*)(sch + (2 * lane + 1) * SC_STR + j));
            float2 gc = __half22float2(*(const __half2*)(sch + (2 * lane + 64) * SC_STR + j));
            float2 gd = __half22float2(*(const __half2*)(sch + (2 * lane + 65) * SC_STR + j));
            float da0 = dA[2 * lane], da1 = dA[2 * lane + 1];
            float da2 = dA[2 * lane + 64], da3 = dA[2 * lane + 65];
            __half2 r0 = __floats2half2_rn(2.0f * ga.x - da0, 2.0f * gb.x - da1);
            __half2 r1 = __floats2half2_rn(2.0f * gc.x - da2, 2.0f * gd.x - da3);
            __half2* d0 = (__half2*)(G + (size_t)(bx * 128 + j) * HW + by * 128);
            d0[lane] = r0;
            d0[lane + 32] = r1;
            __half2 s0 = __floats2half2_rn(2.0f * ga.y - da0, 2.0f * gb.y - da1);
            __half2 s1 = __floats2half2_rn(2.0f * gc.y - da2, 2.0f * gd.y - da3);
            __half2* d1 = (__half2*)(G + (size_t)(bx * 128 + j + 1) * HW + by * 128);
            d1[lane] = s0;
            d1[lane + 32] = s1;
        }
    }
}

// ---------------- 3) per-row top-16 via packed keys + REDUX ----------------
__global__ void __launch_bounds__(256) k_topk() {
    __shared__ uint32_t sc[HW];     // 16KB keys
    __shared__ uint32_t wv[2][8];
    __shared__ uint32_t bc[2];
    int mod = blockIdx.z, n = blockIdx.y, i = blockIdx.x;
    int t = threadIdx.x, w = t >> 5, l = t & 31;
    const uint4* S4 = (const uint4*)(g_scoresh[mod]
                        + (size_t)n * HW * HW + (size_t)i * HW);

    uint32_t myKey = 0;
#pragma unroll
    for (int step = 0; step < 2; step++) {
        int v = t + 256 * step;
        uint4 pk = S4[v];
        int j0 = v * 8;
        uint32_t pw[4] = { pk.x, pk.y, pk.z, pk.w };
#pragma unroll
        for (int q = 0; q < 4; q++) {
            int j = j0 + 2 * q;
            uint32_t h0 = pw[q] & 0xFFFFu, h1 = pw[q] >> 16;
            uint32_t o0 = (h0 & 0x8000u) ? (~h0 & 0xFFFFu) : (h0 | 0x8000u);
            uint32_t o1 = (h1 & 0x8000u) ? (~h1 & 0xFFFFu) : (h1 | 0x8000u);
            uint32_t k0 = (o0 << 12) | (uint32_t)(4095 - j);
            uint32_t k1 = (o1 << 12) | (uint32_t)(4094 - j);
            sc[j] = k0; sc[j + 1] = k1;
            myKey = max(myKey, max(k0, k1));
        }
    }
    __syncthreads();

    int* out = g_knn[mod] + ((size_t)n * HW + i) * KNN;
#pragma unroll 1
    for (int s = 0; s < KNN; s++) {
        int pb = s & 1;
        uint32_t wk = __reduce_max_sync(0xffffffffu, myKey);
        if (l == 0) wv[pb][w] = wk;
        __syncthreads();
        if (t == 0) {
            uint32_t B = wv[pb][0];
#pragma unroll
            for (int u = 1; u < 8; u++) B = max(B, wv[pb][u]);
            bc[pb] = B;
            out[s] = 4095 - (int)(B & 0xFFFu);
        }
        __syncthreads();
        uint32_t best = bc[pb];
        if (myKey == best) {
            int jwin = 4095 - (int)(best & 0xFFFu);
            sc[jwin] = 0;
            uint32_t nk = 0;
#pragma unroll
            for (int q = 0; q < 8; q++)
                nk = max(nk, max(sc[8 * t + q], sc[2048 + 8 * t + q]));
            myKey = nk;
        }
    }
}

// ---------------- 4) A/B tables ----------------
__global__ __launch_bounds__(256) void k_ab(const float* __restrict__ Wr,
                                            const float* __restrict__ Wi) {
    __shared__ float Xs[64][36];
    __shared__ float Ws[32][128];
    int which = blockIdx.y;
    const float* X  = (which == 0 || which == 3) ? g_xt[0] : g_xt[1];
    const float* Wg = (which < 2) ? Wr : Wi;
    bool both = (which == 0 || which == 2);
    int r0 = blockIdx.x * 64;
    int tx = threadIdx.x & 15, ty = threadIdx.x >> 4;

    float acc[4][8];
#pragma unroll
    for (int i = 0; i < 4; i++)
#pragma unroll
        for (int j = 0; j < 8; j++) acc[i][j] = 0.0f;

    for (int k0 = 0; k0 < 128; k0 += 32) {
#pragma unroll
        for (int p = 0; p < 2; p++) {
            int f4 = threadIdx.x + 256 * p;
            int r = f4 >> 3, kq = f4 & 7;
            *(float4*)(&Xs[r][kq * 4]) =
                *(const float4*)(X + (size_t)(r0 + r) * CCH + k0 + kq * 4);
        }
#pragma unroll
        for (int p = 0; p < 4; p++) {
            int f4 = threadIdx.x + 256 * p;
            int kk = f4 >> 5, cq = f4 & 31;
            float4 w = *(const float4*)(Wg + (size_t)(128 + k0 + kk) * CCH + cq * 4);
            if (both) {
                float4 w0 = *(const float4*)(Wg + (size_t)(k0 + kk) * CCH + cq * 4);
                w.x += w0.x; w.y += w0.y; w.z += w0.z; w.w += w0.w;
            }
            *(float4*)(&Ws[kk][cq * 4]) = w;
        }
        __syncthreads();
#pragma unroll 8
        for (int kk = 0; kk < 32; kk++) {
            float a[4], b[8];
#pragma unroll
            for (int i = 0; i < 4; i++) a[i] = Xs[ty + 16 * i][kk];
#pragma unroll
            for (int j = 0; j < 8; j++) b[j] = Ws[kk][tx + 16 * j];
#pragma unroll
            for (int i = 0; i < 4; i++)
#pragma unroll
                for (int j = 0; j < 8; j++) acc[i][j] += a[i] * b[j];
        }
        __syncthreads();
    }
#pragma unroll
    for (int i = 0; i < 4; i++)
#pragma unroll
        for (int j = 0; j < 8; j++)
            g_AB[which][(size_t)(r0 + ty + 16 * i) * CCH + tx + 16 * j] = acc[i][j];
}

// ---------------- 5) pair gather-mean ----------------
__global__ __launch_bounds__(128) void k_pair(const float* __restrict__ br,
                                              const float* __restrict__ bi) {
    __shared__ int sp[256], sq[256];
    int n = blockIdx.y;
    int base = n * PAIRS + blockIdx.x * 256;
    for (int t = threadIdx.x; t < 256; t += 128) {
        sp[t] = g_knn[0][base + t];
        sq[t] = g_knn[1][base + t];
    }
    __syncthreads();
    int c = threadIdx.x;
    float brc = br[c], bic = bi[c];
    float aR = 0.0f, aI = 0.0f;
#pragma unroll 4
    for (int t = 0; t < 256; t++) {
        int p = sp[t], q = sq[t];
        float fr = g_AB[0][p * CCH + c] - g_AB[1][q * CCH + c] + brc;
        aR += (fr >= 0.0f) ? fr : 0.01f * fr;
        float fi = g_AB[2][q * CCH + c] - g_AB[3][p * CCH + c] + bic;
        aI += (fi >= 0.0f) ? fi : 0.01f * fi;
    }
    int b = n * 256 + blockIdx.x;
    g_partial[b][c]       = aR;
    g_partial[b][c + 128] = aI;
}

// ---------------- 6) first-level reduce: 256 partials -> 16 per n ----------------
__global__ void k_reduce16() {
    int b = blockIdx.x;                 // 64 blocks: n = b>>4, group = b&15
    int n = b >> 4, r0 = (b & 15) * 16;
    int d = threadIdx.x;
    float s = 0.0f;
#pragma unroll
    for (int r = 0; r < 16; r++) s += g_partial[n * 256 + r0 + r][d];
    g_p2[b][d] = s;
}

// ---------------- 7) final reduce + SE gate ----------------
__global__ void k_se(const float* __restrict__ w1, const float* __restrict__ b1,
                     const float* __restrict__ w2, const float* __restrict__ b2) {
    __shared__ float m_s[1024];
    __shared__ float tm[NB][8];
    int tid = threadIdx.x;              // 512
#pragma unroll
    for (int it = 0; it < 2; it++) {
        int idx = tid + 512 * it;
        int n = idx >> 8, d = idx & 255;
        float s = 0.0f;
#pragma unroll
        for (int g = 0; g < 16; g++) s += g_p2[n * 16 + g][d];
        m_s[idx] = s * (1.0f / (float)PAIRS);
    }
    __syncthreads();
    if (tid < 32) {
        int n = tid >> 3, j = tid & 7;
        float s = b1[j];
        for (int d = 0; d < 256; d++) s += m_s[n * 256 + d] * w1[d * 8 + j];
        tm[n][j] = (s >= 0.0f) ? s : 0.01f * s;
    }
    __syncthreads();
    int n = tid >> 7, c = tid & 127;
    float s = b2[c];
#pragma unroll
    for (int j = 0; j < 8; j++) s += tm[n][j] * w2[j * 128 + c];
    g_gate[n * 128 + c] = 1.0f / (1.0f + expf(-s));
}

// ---------------- 8) gated blend + relu ----------------
__global__ void k_out(const float* __restrict__ g1, const float* __restrict__ g2,
                      float* __restrict__ out) {
    int o = blockIdx.x * blockDim.x + threadIdx.x;
    if (o >= NB * CCH * HW) return;
    int nc = o >> 12;
    float g = g_gate[nc];
    float v = g1[0] * g * g_pool[0][o] + g2[0] * (1.0f - g) * g_pool[1][o];
    out[o] = fmaxf(v, 0.0f);
}

// ---------------- launch ----------------
extern "C" void kernel_launch(void* const* d_in, const int* in_sizes, int n_in,
                              void* d_out, int out_size) {
    const float* rgb = (const float*)d_in[0];
    const float* ir  = (const float*)d_in[1];
    const float* Wr  = (const float*)d_in[2];
    const float* br  = (const float*)d_in[3];
    const float* Wi  = (const float*)d_in[4];
    const float* bi  = (const float*)d_in[5];
    const float* w1  = (const float*)d_in[6];
    const float* b1  = (const float*)d_in[7];
    const float* w2  = (const float*)d_in[8];
    const float* b2  = (const float*)d_in[9];
    const float* g1  = (const float*)d_in[10];
    const float* g2  = (const float*)d_in[11];
    float* out = (float*)d_out;

    cudaFuncSetAttribute(k_gram_tri, cudaFuncAttributeMaxDynamicSharedMemorySize, GS_TOTAL);

    k_tnorm<<<dim3(128, 4, 2), 256>>>(rgb, ir);   // fused pool+transpose+norm
    k_ab<<<dim3(64, 4), 256>>>(Wr, Wi);

    k_gram_tri<<<dim3(528, 8), 256, GS_TOTAL>>>();   // triangular, fp16 overlay epilogue
    k_topk<<<dim3(4096, 4, 2), 256>>>();             // packed-key REDUX top-16

    k_pair<<<dim3(256, 4), 128>>>(br, bi);
    k_reduce16<<<64, 256>>>();
    k_se<<<1, 512>>>(w1, b1, w2, b2);
    k_out<<<8192, 256>>>(g1, g2, out);
}